// round 10
// baseline (speedup 1.0000x reference)
#include <cuda_runtime.h>
#include <cuda_bf16.h>
#include <math.h>

#define N_NODES 50000
#define N_EDGES 800000
#define D_IN    128
#define D_HID   256
#define N_CLS   16
#define N_PROT  512

#define SCAN_TILE 1024
#define N_TILES   ((N_NODES + SCAN_TILE - 1) / SCAN_TILE)   // 49

// ---------------- scratch (device globals; no allocs allowed) ----------------
__device__ float g_dis[N_NODES];
__device__ int   g_indeg[N_NODES];
__device__ int   g_cursor[N_NODES];
__device__ int   g_rowptr[N_NODES + 1];
__device__ int   g_partial[N_TILES];
__device__ int   g_csr_src[N_EDGES];
__device__ float g_csr_w [N_EDGES];
__device__ float g_xw[(size_t)N_NODES * D_HID];
__device__ float g_h [(size_t)N_NODES * D_HID];
__device__ float g_xrel_scratch[(size_t)N_NODES * N_PROT];
__device__ float g_anchors [(size_t)N_PROT * D_HID];
__device__ float g_anchorT [(size_t)D_HID * N_PROT];
__device__ float g_outproto[(size_t)N_PROT * N_CLS];

// ---------------- f32x2 packed helpers -----------------
typedef unsigned long long u64;

__device__ __forceinline__ u64 fma2(u64 a, u64 b, u64 c) {
    u64 d;
    asm("fma.rn.f32x2 %0, %1, %2, %3;" : "=l"(d) : "l"(a), "l"(b), "l"(c));
    return d;
}
__device__ __forceinline__ u64 pack2(float lo, float hi) {
    u64 d;
    asm("mov.b64 %0, {%1, %2};" : "=l"(d) : "f"(lo), "f"(hi));
    return d;
}
__device__ __forceinline__ void unpack2(u64 v, float& lo, float& hi) {
    asm("mov.b64 {%0, %1}, %2;" : "=f"(lo), "=f"(hi) : "l"(v));
}

// ---------------- graph prep ----------------
__global__ void k_zero_counts() {
    int i = blockIdx.x * blockDim.x + threadIdx.x;
    if (i < N_NODES) { g_indeg[i] = 0; g_cursor[i] = 0; }
}

__global__ void k_count_deg(const int* __restrict__ dst) {
    int e = blockIdx.x * blockDim.x + threadIdx.x;
    if (e < N_EDGES) {
        int d = dst[e];
        if (d >= 0 && d < N_NODES) atomicAdd(&g_indeg[d], 1);
    }
}

__global__ void k_dis() {
    int i = blockIdx.x * blockDim.x + threadIdx.x;
    if (i < N_NODES) {
        float deg = (float)(g_indeg[i] + 1);
        g_dis[i] = 1.0f / sqrtf(deg);
    }
}

__global__ void k_scan_partial() {
    __shared__ int sh[SCAN_TILE];
    int b = blockIdx.x, t = threadIdx.x;
    int i = b * SCAN_TILE + t;
    sh[t] = (i < N_NODES) ? g_indeg[i] : 0;
    __syncthreads();
    for (int off = SCAN_TILE / 2; off > 0; off >>= 1) {
        if (t < off) sh[t] += sh[t + off];
        __syncthreads();
    }
    if (t == 0) g_partial[b] = sh[0];
}

__global__ void k_scan_offsets() {
    if (threadIdx.x == 0) {
        int acc = 0;
        for (int i = 0; i < N_TILES; i++) {
            int v = g_partial[i];
            g_partial[i] = acc;
            acc += v;
        }
    }
}

__global__ void k_scan_final() {
    __shared__ int sh[SCAN_TILE];
    int b = blockIdx.x, t = threadIdx.x;
    int i = b * SCAN_TILE + t;
    int v = (i < N_NODES) ? g_indeg[i] : 0;
    sh[t] = v;
    __syncthreads();
    for (int off = 1; off < SCAN_TILE; off <<= 1) {
        int u = (t >= off) ? sh[t - off] : 0;
        __syncthreads();
        sh[t] += u;
        __syncthreads();
    }
    if (i < N_NODES) g_rowptr[i + 1] = sh[t] + g_partial[b];
    if (b == 0 && t == 0) g_rowptr[0] = 0;
}

// fill CSR and precompute per-edge norm weight (breaks dependent-load chain in agg)
__global__ void k_fill_csr(const int* __restrict__ src,
                           const int* __restrict__ dst) {
    int e = blockIdx.x * blockDim.x + threadIdx.x;
    if (e < N_EDGES) {
        int d = dst[e];
        int s = src[e];
        if (d < 0 || d >= N_NODES || s < 0 || s >= N_NODES) return;
        int pos = atomicAdd(&g_cursor[d], 1);
        int idx = g_rowptr[d] + pos;
        if (idx >= 0 && idx < N_EDGES) {
            g_csr_src[idx] = s;
            g_csr_w[idx]   = g_dis[s] * g_dis[d];
        }
    }
}

// ---------- FFMA2 GEMM: 64x64 tile, 256 threads, 4x4 microtile ---------------
// B stored as duplicated (b,b) u64, columns interleaved (tx + 16*c) -> conflict-free
__device__ __forceinline__ void gemm_body(const float* __restrict__ A,
                                          const float* __restrict__ B,
                                          float* __restrict__ C,
                                          int M, int N, int K) {
    __shared__ float As[16][64];   // 4 KB  [k][m]
    __shared__ u64   Bs[16][64];   // 8 KB  [k][n] dup pairs, identity col layout
    int bm = blockIdx.y * 64;
    int bn = blockIdx.x * 64;
    int t = threadIdx.x;
    int tx = t & 15, ty = t >> 4;

    u64 acc2[2][4];
#pragma unroll
    for (int r = 0; r < 2; r++)
#pragma unroll
        for (int c = 0; c < 4; c++) acc2[r][c] = 0ULL;

    for (int k0 = 0; k0 < K; k0 += 16) {
        {   // A tile: 64 rows x 16 k
            int m = t >> 2;
            int kq = t & 3;
            float4 v = make_float4(0.f, 0.f, 0.f, 0.f);
            if (bm + m < M)
                v = *(const float4*)&A[(size_t)(bm + m) * K + k0 + kq * 4];
            As[kq * 4 + 0][m] = v.x;
            As[kq * 4 + 1][m] = v.y;
            As[kq * 4 + 2][m] = v.z;
            As[kq * 4 + 3][m] = v.w;
        }
        {   // B tile: 16 k x 64 n, stored as dup pairs at identity columns
            int kk = t >> 4;
            int nq = t & 15;
            float4 v = *(const float4*)&B[(size_t)(k0 + kk) * N + bn + nq * 4];
            Bs[kk][nq * 4 + 0] = pack2(v.x, v.x);
            Bs[kk][nq * 4 + 1] = pack2(v.y, v.y);
            Bs[kk][nq * 4 + 2] = pack2(v.z, v.z);
            Bs[kk][nq * 4 + 3] = pack2(v.w, v.w);
        }
        __syncthreads();
#pragma unroll
        for (int kk = 0; kk < 16; kk++) {
            u64 a0 = *(const u64*)&As[kk][ty * 4 + 0];   // broadcast within warp
            u64 a1 = *(const u64*)&As[kk][ty * 4 + 2];
            u64 bb0 = Bs[kk][tx + 0];                    // interleaved cols: no conflicts
            u64 bb1 = Bs[kk][tx + 16];
            u64 bb2 = Bs[kk][tx + 32];
            u64 bb3 = Bs[kk][tx + 48];
            acc2[0][0] = fma2(a0, bb0, acc2[0][0]);
            acc2[0][1] = fma2(a0, bb1, acc2[0][1]);
            acc2[0][2] = fma2(a0, bb2, acc2[0][2]);
            acc2[0][3] = fma2(a0, bb3, acc2[0][3]);
            acc2[1][0] = fma2(a1, bb0, acc2[1][0]);
            acc2[1][1] = fma2(a1, bb1, acc2[1][1]);
            acc2[1][2] = fma2(a1, bb2, acc2[1][2]);
            acc2[1][3] = fma2(a1, bb3, acc2[1][3]);
        }
        __syncthreads();
    }
    // writeout: thread's cols are bn + tx + 16*c (16 lanes consecutive -> 64B)
#pragma unroll
    for (int r2 = 0; r2 < 2; r2++) {
#pragma unroll
        for (int c = 0; c < 4; c++) {
            float lo, hi;
            unpack2(acc2[r2][c], lo, hi);
            int m0 = bm + ty * 4 + r2 * 2;
            int n  = bn + tx + 16 * c;
            if (m0 < M)     C[(size_t)m0 * N + n] = lo;
            if (m0 + 1 < M) C[(size_t)(m0 + 1) * N + n] = hi;
        }
    }
}

__global__ void __launch_bounds__(256, 4)
k_gemm_xw0(const float* __restrict__ x, const float* __restrict__ W0) {
    gemm_body(x, W0, g_xw, N_NODES, D_HID, D_IN);
}
__global__ void __launch_bounds__(256, 4)
k_gemm_hw1(const float* __restrict__ W1) {
    gemm_body(g_h, W1, g_xw, N_NODES, D_HID, D_HID);
}
__global__ void __launch_bounds__(256, 4)
k_gemm_xrel(float* __restrict__ xrel) {
    gemm_body(g_h, g_anchorT, xrel, N_NODES, N_PROT, D_HID);
}
__global__ void __launch_bounds__(256, 4)
k_gemm_xrel_scratch() {
    gemm_body(g_h, g_anchorT, g_xrel_scratch, N_NODES, N_PROT, D_HID);
}

// ------- GCN aggregation v2: precomputed weights, x4 unroll, opt. rownorm ----
__global__ void k_aggregate(const float* __restrict__ bias, int do_relu, int do_norm) {
    int node = blockIdx.x;
    int t = threadIdx.x;  // 64 threads x float4 = 256 cols
    int beg = g_rowptr[node], end = g_rowptr[node + 1];
    const float4* xw4 = (const float4*)g_xw;
    float4 acc = make_float4(0.f, 0.f, 0.f, 0.f);

    int e = beg;
    for (; e + 4 <= end; e += 4) {
        int   s0 = g_csr_src[e],   s1 = g_csr_src[e+1];
        int   s2 = g_csr_src[e+2], s3 = g_csr_src[e+3];
        float w0 = g_csr_w[e],     w1 = g_csr_w[e+1];
        float w2 = g_csr_w[e+2],   w3 = g_csr_w[e+3];
        float4 v0 = xw4[(size_t)s0 * 64 + t];
        float4 v1 = xw4[(size_t)s1 * 64 + t];
        float4 v2 = xw4[(size_t)s2 * 64 + t];
        float4 v3 = xw4[(size_t)s3 * 64 + t];
        acc.x += w0*v0.x + w1*v1.x + w2*v2.x + w3*v3.x;
        acc.y += w0*v0.y + w1*v1.y + w2*v2.y + w3*v3.y;
        acc.z += w0*v0.z + w1*v1.z + w2*v2.z + w3*v3.z;
        acc.w += w0*v0.w + w1*v1.w + w2*v2.w + w3*v3.w;
    }
    for (; e < end; e++) {
        int s = g_csr_src[e];
        float w = g_csr_w[e];
        float4 v = xw4[(size_t)s * 64 + t];
        acc.x += w*v.x; acc.y += w*v.y; acc.z += w*v.z; acc.w += w*v.w;
    }
    {   // self loop
        float dn = g_dis[node];
        float w = dn * dn;
        float4 v = xw4[(size_t)node * 64 + t];
        acc.x += w*v.x; acc.y += w*v.y; acc.z += w*v.z; acc.w += w*v.w;
    }
    float4 bv = ((const float4*)bias)[t];
    acc.x += bv.x; acc.y += bv.y; acc.z += bv.z; acc.w += bv.w;
    if (do_relu) {
        acc.x = fmaxf(acc.x, 0.f); acc.y = fmaxf(acc.y, 0.f);
        acc.z = fmaxf(acc.z, 0.f); acc.w = fmaxf(acc.w, 0.f);
    }
    if (do_norm) {   // fused L2 row-normalize
        float s = acc.x*acc.x + acc.y*acc.y + acc.z*acc.z + acc.w*acc.w;
#pragma unroll
        for (int off = 16; off >= 1; off >>= 1)
            s += __shfl_xor_sync(0xFFFFFFFFu, s, off);
        __shared__ float ws[2];
        if ((t & 31) == 0) ws[t >> 5] = s;
        __syncthreads();
        s = ws[0] + ws[1];
        float r = 1.0f / sqrtf(s);
        acc.x *= r; acc.y *= r; acc.z *= r; acc.w *= r;
    }
    ((float4*)g_h)[(size_t)node * 64 + t] = acc;
}

// ---------------- anchor gather (rows + transposed) --------------------------
__global__ void k_gather_anchors(const int* __restrict__ prot) {
    int p = blockIdx.x;
    int t = threadIdx.x;  // 256
    int nl = prot[p];
    int node = (nl >= 0 && nl < N_NODES) ? nl : 0;
    float v = g_h[(size_t)node * D_HID + t];
    g_anchors[(size_t)p * D_HID + t] = v;
    g_anchorT[(size_t)t * N_PROT + p] = v;
}

// ---------------- prototype head: log_softmax(lin(anchors)) ------------------
__global__ void k_proto_head(const float* __restrict__ Wl1, const float* __restrict__ bl1,
                             const float* __restrict__ Wl2, const float* __restrict__ bl2,
                             float* __restrict__ out_proto_dst, int write_out) {
    int p = blockIdx.x;
    int t = threadIdx.x;  // 256
    __shared__ float a[D_HID];
    __shared__ float h1[D_HID];
    __shared__ float z[N_CLS];
    a[t] = g_anchors[(size_t)p * D_HID + t];
    __syncthreads();
    float s = bl1[t];
#pragma unroll 4
    for (int k = 0; k < D_HID; k++) s += a[k] * Wl1[(size_t)k * D_HID + t];
    h1[t] = fmaxf(s, 0.0f);
    __syncthreads();
    if (t < N_CLS) {
        float s2 = bl2[t];
#pragma unroll 4
        for (int k = 0; k < D_HID; k++) s2 += h1[k] * Wl2[(size_t)k * N_CLS + t];
        z[t] = s2;
    }
    __syncthreads();
    if (t < N_CLS) {
        float m = z[0];
#pragma unroll
        for (int j = 1; j < N_CLS; j++) m = fmaxf(m, z[j]);
        float se = 0.f;
#pragma unroll
        for (int j = 0; j < N_CLS; j++) se += expf(z[j] - m);
        float v = z[t] - m - logf(se);
        g_outproto[(size_t)p * N_CLS + t] = v;
        if (write_out) out_proto_dst[(size_t)p * N_CLS + t] = v;
    }
}

// ---------------- out = log_softmax(x_rel @ out_proto) -----------------------
__device__ __forceinline__ void out_head_body(const float* __restrict__ xr_base,
                                              float* __restrict__ out) {
    __shared__ float ps[N_PROT * N_CLS];  // 32KB
    __shared__ float z[8][N_CLS];
    int t = threadIdx.x;
    for (int i = t; i < N_PROT * N_CLS; i += 128) ps[i] = g_outproto[i];
    __syncthreads();
    int g = t >> 4;
    int c = t & 15;
    int node = blockIdx.x * 8 + g;
    const float* xr = xr_base + (size_t)node * N_PROT;
    float s0 = 0.f, s1 = 0.f, s2 = 0.f, s3 = 0.f;
    for (int p = 0; p < N_PROT; p += 4) {
        s0 += xr[p + 0] * ps[(p + 0) * N_CLS + c];
        s1 += xr[p + 1] * ps[(p + 1) * N_CLS + c];
        s2 += xr[p + 2] * ps[(p + 2) * N_CLS + c];
        s3 += xr[p + 3] * ps[(p + 3) * N_CLS + c];
    }
    float s = (s0 + s1) + (s2 + s3);
    z[g][c] = s;
    __syncthreads();
    float m = z[g][0];
#pragma unroll
    for (int j = 1; j < N_CLS; j++) m = fmaxf(m, z[g][j]);
    float se = 0.f;
#pragma unroll
    for (int j = 0; j < N_CLS; j++) se += expf(z[g][j] - m);
    out[(size_t)node * N_CLS + c] = s - m - logf(se);
}

__global__ void k_out_head(const float* __restrict__ xrel, float* __restrict__ out) {
    out_head_body(xrel, out);
}
__global__ void k_out_head_scratch(float* __restrict__ out) {
    out_head_body(g_xrel_scratch, out);
}

// ---------------- launcher ----------------
extern "C" void kernel_launch(void* const* d_in, const int* in_sizes, int n_in,
                              void* d_out, int out_size) {
    const float* x    = (const float*)d_in[0];
    const int*   ei   = (const int*)d_in[1];     // int32
    const int*   prot = (const int*)d_in[2];     // int32

    int wbase = (in_sizes[3] <= 1) ? 4 : 3;
    const float* W0  = (const float*)d_in[wbase + 0];
    const float* b0  = (const float*)d_in[wbase + 1];
    const float* W1  = (const float*)d_in[wbase + 2];
    const float* b1  = (const float*)d_in[wbase + 3];
    const float* Wl1 = (const float*)d_in[wbase + 4];
    const float* bl1 = (const float*)d_in[wbase + 5];
    const float* Wl2 = (const float*)d_in[wbase + 6];
    const float* bl2 = (const float*)d_in[wbase + 7];

    const size_t SZ_OUT   = (size_t)N_NODES * N_CLS;
    const size_t SZ_XREL  = (size_t)N_NODES * N_PROT;
    const size_t SZ_PROTO = (size_t)N_PROT * N_CLS;

    float* out = (float*)d_out;
    bool full = ((size_t)out_size >= SZ_OUT + SZ_XREL + SZ_PROTO);
    float* xrel = nullptr;
    float* out_proto = nullptr;
    if (full) {
        xrel      = out + SZ_OUT;
        out_proto = xrel + SZ_XREL;
    }

    const int* src = ei;
    const int* dst = ei + N_EDGES;

    const int MB = (N_NODES + 63) / 64;   // 782
    dim3 g1(D_HID / 64, MB);
    dim3 g2(N_PROT / 64, MB);

    // launches 0-2: prep that k_dis needs
    k_zero_counts<<<(N_NODES + 255) / 256, 256>>>();
    k_count_deg<<<(N_EDGES + 255) / 256, 256>>>(dst);
    k_dis<<<(N_NODES + 255) / 256, 256>>>();
    // launch 3: gemm_xw0 (independent of graph prep) -> gets ncu-profiled
    k_gemm_xw0<<<g1, 256>>>(x, W0);
    // remaining graph prep
    k_scan_partial<<<N_TILES, SCAN_TILE>>>();
    k_scan_offsets<<<1, 32>>>();
    k_scan_final<<<N_TILES, SCAN_TILE>>>();
    k_fill_csr<<<(N_EDGES + 255) / 256, 256>>>(src, dst);

    // layer 0: h = relu(aggregate(xw) + b0)
    k_aggregate<<<N_NODES, 64>>>(b0, 1, 0);
    // layer 1: h = normalize(aggregate(h @ W1) + b1)   (rownorm fused)
    k_gemm_hw1<<<g1, 256>>>(W1);
    k_aggregate<<<N_NODES, 64>>>(b1, 0, 1);

    k_gather_anchors<<<N_PROT, 256>>>(prot);
    k_proto_head<<<N_PROT, 256>>>(Wl1, bl1, Wl2, bl2, out_proto, full ? 1 : 0);

    if (full) {
        k_gemm_xrel<<<g2, 256>>>(xrel);
        k_out_head<<<N_NODES / 8, 128>>>(xrel, out);
    } else {
        k_gemm_xrel_scratch<<<g2, 256>>>();
        k_out_head_scratch<<<N_NODES / 8, 128>>>(out);
    }
}

// round 11
// speedup vs baseline: 1.3130x; 1.3130x over previous
#include <cuda_runtime.h>
#include <cuda_bf16.h>
#include <math.h>

#define N_NODES 50000
#define N_EDGES 800000
#define D_IN    128
#define D_HID   256
#define N_CLS   16
#define N_PROT  512

#define SCAN_TILE 1024
#define N_TILES   ((N_NODES + SCAN_TILE - 1) / SCAN_TILE)   // 49

// ---------------- scratch (device globals; no allocs allowed) ----------------
__device__ float g_dis[N_NODES];
__device__ int   g_indeg[N_NODES];
__device__ int   g_cursor[N_NODES];
__device__ int   g_rowptr[N_NODES + 1];
__device__ int   g_partial[N_TILES];
__device__ int   g_csr_src[N_EDGES];
__device__ float g_csr_w [N_EDGES];
__device__ float g_xw[(size_t)N_NODES * D_HID];
__device__ float g_h [(size_t)N_NODES * D_HID];
__device__ float g_xrel_scratch[(size_t)N_NODES * N_PROT];
__device__ float g_anchors [(size_t)N_PROT * D_HID];
__device__ float g_anchorT [(size_t)D_HID * N_PROT];
__device__ float g_outproto[(size_t)N_PROT * N_CLS];

// ---------------- f32x2 packed helpers -----------------
typedef unsigned long long u64;

__device__ __forceinline__ u64 fma2(u64 a, u64 b, u64 c) {
    u64 d;
    asm("fma.rn.f32x2 %0, %1, %2, %3;" : "=l"(d) : "l"(a), "l"(b), "l"(c));
    return d;
}
__device__ __forceinline__ u64 pack2(float lo, float hi) {
    u64 d;
    asm("mov.b64 %0, {%1, %2};" : "=l"(d) : "f"(lo), "f"(hi));
    return d;
}
__device__ __forceinline__ void unpack2(u64 v, float& lo, float& hi) {
    asm("mov.b64 {%0, %1}, %2;" : "=f"(lo), "=f"(hi) : "l"(v));
}

// ---------------- graph prep ----------------
__global__ void k_zero_counts() {
    int i = blockIdx.x * blockDim.x + threadIdx.x;
    if (i < N_NODES) { g_indeg[i] = 0; g_cursor[i] = 0; }
}

__global__ void k_count_deg(const int* __restrict__ dst) {
    int e = blockIdx.x * blockDim.x + threadIdx.x;
    if (e < N_EDGES) {
        int d = dst[e];
        if (d >= 0 && d < N_NODES) atomicAdd(&g_indeg[d], 1);
    }
}

__global__ void k_dis() {
    int i = blockIdx.x * blockDim.x + threadIdx.x;
    if (i < N_NODES) {
        float deg = (float)(g_indeg[i] + 1);
        g_dis[i] = 1.0f / sqrtf(deg);
    }
}

__global__ void k_scan_partial() {
    __shared__ int sh[SCAN_TILE];
    int b = blockIdx.x, t = threadIdx.x;
    int i = b * SCAN_TILE + t;
    sh[t] = (i < N_NODES) ? g_indeg[i] : 0;
    __syncthreads();
    for (int off = SCAN_TILE / 2; off > 0; off >>= 1) {
        if (t < off) sh[t] += sh[t + off];
        __syncthreads();
    }
    if (t == 0) g_partial[b] = sh[0];
}

__global__ void k_scan_offsets() {
    if (threadIdx.x == 0) {
        int acc = 0;
        for (int i = 0; i < N_TILES; i++) {
            int v = g_partial[i];
            g_partial[i] = acc;
            acc += v;
        }
    }
}

__global__ void k_scan_final() {
    __shared__ int sh[SCAN_TILE];
    int b = blockIdx.x, t = threadIdx.x;
    int i = b * SCAN_TILE + t;
    int v = (i < N_NODES) ? g_indeg[i] : 0;
    sh[t] = v;
    __syncthreads();
    for (int off = 1; off < SCAN_TILE; off <<= 1) {
        int u = (t >= off) ? sh[t - off] : 0;
        __syncthreads();
        sh[t] += u;
        __syncthreads();
    }
    if (i < N_NODES) g_rowptr[i + 1] = sh[t] + g_partial[b];
    if (b == 0 && t == 0) g_rowptr[0] = 0;
}

// fill CSR and precompute per-edge norm weight
__global__ void k_fill_csr(const int* __restrict__ src,
                           const int* __restrict__ dst) {
    int e = blockIdx.x * blockDim.x + threadIdx.x;
    if (e < N_EDGES) {
        int d = dst[e];
        int s = src[e];
        if (d < 0 || d >= N_NODES || s < 0 || s >= N_NODES) return;
        int pos = atomicAdd(&g_cursor[d], 1);
        int idx = g_rowptr[d] + pos;
        if (idx >= 0 && idx < N_EDGES) {
            g_csr_src[idx] = s;
            g_csr_w[idx]   = g_dis[s] * g_dis[d];
        }
    }
}

// ---------- FFMA2 GEMM: 128x128 tile, 256 threads, 8x8 microtile -------------
// A row-pairs broadcast within warp (LDS.64); B as duplicated (b,b) u64 pairs,
// interleaved columns (tx + 16*j) -> broadcast LDS.64, no packs in mainloop.
// 1.33 flop/smem-byte -> fma-pipe becomes the binder (vs 0.67 in 4x4 version).
__device__ __forceinline__ void gemm_body(const float* __restrict__ A,
                                          const float* __restrict__ B,
                                          float* __restrict__ C,
                                          int M, int N, int K) {
    __shared__ float As[16][128];   // 8 KB, [k][m]
    __shared__ u64   Bs[16][128];   // 16 KB, [k][n] dup pairs
    int t = threadIdx.x;
    int tx = t & 15, ty = t >> 4;
    int bm = blockIdx.y * 128;
    int bn = blockIdx.x * 128;

    u64 acc[4][8];
#pragma unroll
    for (int i = 0; i < 4; i++)
#pragma unroll
        for (int j = 0; j < 8; j++) acc[i][j] = 0ULL;

    for (int k0 = 0; k0 < K; k0 += 16) {
        {   // A tile: 128 rows x 16 k; thread loads 8 k-values of one row
            int m = t >> 1;
            int kq = (t & 1) * 8;
            int gm = bm + m;
            float4 v0 = make_float4(0.f, 0.f, 0.f, 0.f), v1 = v0;
            if (gm < M) {
                v0 = *(const float4*)&A[(size_t)gm * K + k0 + kq];
                v1 = *(const float4*)&A[(size_t)gm * K + k0 + kq + 4];
            }
            As[kq + 0][m] = v0.x; As[kq + 1][m] = v0.y;
            As[kq + 2][m] = v0.z; As[kq + 3][m] = v0.w;
            As[kq + 4][m] = v1.x; As[kq + 5][m] = v1.y;
            As[kq + 6][m] = v1.z; As[kq + 7][m] = v1.w;
        }
        {   // B tile: 16 k x 128 n; interleaved cols, dup-pair stores
            int kk = t >> 4;
            const float* Br = &B[(size_t)(k0 + kk) * N + bn];
#pragma unroll
            for (int j = 0; j < 8; j++) {
                float b = Br[tx + 16 * j];
                Bs[kk][tx + 16 * j] = pack2(b, b);
            }
        }
        __syncthreads();
#pragma unroll
        for (int kk = 0; kk < 16; kk++) {
            u64 a[4], bb[8];
#pragma unroll
            for (int i = 0; i < 4; i++)
                a[i] = *(const u64*)&As[kk][ty * 8 + 2 * i];   // warp-broadcast
#pragma unroll
            for (int j = 0; j < 8; j++)
                bb[j] = Bs[kk][tx + 16 * j];                   // warp-broadcast
#pragma unroll
            for (int i = 0; i < 4; i++)
#pragma unroll
                for (int j = 0; j < 8; j++)
                    acc[i][j] = fma2(a[i], bb[j], acc[i][j]);
        }
        __syncthreads();
    }
    // writeout: cols tx + 16*j -> 16 consecutive lanes = 64B segments
#pragma unroll
    for (int i = 0; i < 4; i++) {
        int m0 = bm + ty * 8 + 2 * i;
#pragma unroll
        for (int j = 0; j < 8; j++) {
            float lo, hi;
            unpack2(acc[i][j], lo, hi);
            int n = bn + tx + 16 * j;
            if (m0 < M)     C[(size_t)m0 * N + n] = lo;
            if (m0 + 1 < M) C[(size_t)(m0 + 1) * N + n] = hi;
        }
    }
}

__global__ void __launch_bounds__(256, 2)
k_gemm_xw0(const float* __restrict__ x, const float* __restrict__ W0) {
    gemm_body(x, W0, g_xw, N_NODES, D_HID, D_IN);
}
__global__ void __launch_bounds__(256, 2)
k_gemm_hw1(const float* __restrict__ W1) {
    gemm_body(g_h, W1, g_xw, N_NODES, D_HID, D_HID);
}
__global__ void __launch_bounds__(256, 2)
k_gemm_xrel(float* __restrict__ xrel) {
    gemm_body(g_h, g_anchorT, xrel, N_NODES, N_PROT, D_HID);
}
__global__ void __launch_bounds__(256, 2)
k_gemm_xrel_scratch() {
    gemm_body(g_h, g_anchorT, g_xrel_scratch, N_NODES, N_PROT, D_HID);
}

// ------- GCN aggregation v2: precomputed weights, x4 unroll, opt. rownorm ----
__global__ void k_aggregate(const float* __restrict__ bias, int do_relu, int do_norm) {
    int node = blockIdx.x;
    int t = threadIdx.x;  // 64 threads x float4 = 256 cols
    int beg = g_rowptr[node], end = g_rowptr[node + 1];
    const float4* xw4 = (const float4*)g_xw;
    float4 acc = make_float4(0.f, 0.f, 0.f, 0.f);

    int e = beg;
    for (; e + 4 <= end; e += 4) {
        int   s0 = g_csr_src[e],   s1 = g_csr_src[e+1];
        int   s2 = g_csr_src[e+2], s3 = g_csr_src[e+3];
        float w0 = g_csr_w[e],     w1 = g_csr_w[e+1];
        float w2 = g_csr_w[e+2],   w3 = g_csr_w[e+3];
        float4 v0 = xw4[(size_t)s0 * 64 + t];
        float4 v1 = xw4[(size_t)s1 * 64 + t];
        float4 v2 = xw4[(size_t)s2 * 64 + t];
        float4 v3 = xw4[(size_t)s3 * 64 + t];
        acc.x += w0*v0.x + w1*v1.x + w2*v2.x + w3*v3.x;
        acc.y += w0*v0.y + w1*v1.y + w2*v2.y + w3*v3.y;
        acc.z += w0*v0.z + w1*v1.z + w2*v2.z + w3*v3.z;
        acc.w += w0*v0.w + w1*v1.w + w2*v2.w + w3*v3.w;
    }
    for (; e < end; e++) {
        int s = g_csr_src[e];
        float w = g_csr_w[e];
        float4 v = xw4[(size_t)s * 64 + t];
        acc.x += w*v.x; acc.y += w*v.y; acc.z += w*v.z; acc.w += w*v.w;
    }
    {   // self loop
        float dn = g_dis[node];
        float w = dn * dn;
        float4 v = xw4[(size_t)node * 64 + t];
        acc.x += w*v.x; acc.y += w*v.y; acc.z += w*v.z; acc.w += w*v.w;
    }
    float4 bv = ((const float4*)bias)[t];
    acc.x += bv.x; acc.y += bv.y; acc.z += bv.z; acc.w += bv.w;
    if (do_relu) {
        acc.x = fmaxf(acc.x, 0.f); acc.y = fmaxf(acc.y, 0.f);
        acc.z = fmaxf(acc.z, 0.f); acc.w = fmaxf(acc.w, 0.f);
    }
    if (do_norm) {   // fused L2 row-normalize
        float s = acc.x*acc.x + acc.y*acc.y + acc.z*acc.z + acc.w*acc.w;
#pragma unroll
        for (int off = 16; off >= 1; off >>= 1)
            s += __shfl_xor_sync(0xFFFFFFFFu, s, off);
        __shared__ float ws[2];
        if ((t & 31) == 0) ws[t >> 5] = s;
        __syncthreads();
        s = ws[0] + ws[1];
        float r = 1.0f / sqrtf(s);
        acc.x *= r; acc.y *= r; acc.z *= r; acc.w *= r;
    }
    ((float4*)g_h)[(size_t)node * 64 + t] = acc;
}

// ---------------- anchor gather (rows + transposed) --------------------------
__global__ void k_gather_anchors(const int* __restrict__ prot) {
    int p = blockIdx.x;
    int t = threadIdx.x;  // 256
    int nl = prot[p];
    int node = (nl >= 0 && nl < N_NODES) ? nl : 0;
    float v = g_h[(size_t)node * D_HID + t];
    g_anchors[(size_t)p * D_HID + t] = v;
    g_anchorT[(size_t)t * N_PROT + p] = v;
}

// ---------------- prototype head: log_softmax(lin(anchors)) ------------------
__global__ void k_proto_head(const float* __restrict__ Wl1, const float* __restrict__ bl1,
                             const float* __restrict__ Wl2, const float* __restrict__ bl2,
                             float* __restrict__ out_proto_dst, int write_out) {
    int p = blockIdx.x;
    int t = threadIdx.x;  // 256
    __shared__ float a[D_HID];
    __shared__ float h1[D_HID];
    __shared__ float z[N_CLS];
    a[t] = g_anchors[(size_t)p * D_HID + t];
    __syncthreads();
    float s = bl1[t];
#pragma unroll 4
    for (int k = 0; k < D_HID; k++) s += a[k] * Wl1[(size_t)k * D_HID + t];
    h1[t] = fmaxf(s, 0.0f);
    __syncthreads();
    if (t < N_CLS) {
        float s2 = bl2[t];
#pragma unroll 4
        for (int k = 0; k < D_HID; k++) s2 += h1[k] * Wl2[(size_t)k * N_CLS + t];
        z[t] = s2;
    }
    __syncthreads();
    if (t < N_CLS) {
        float m = z[0];
#pragma unroll
        for (int j = 1; j < N_CLS; j++) m = fmaxf(m, z[j]);
        float se = 0.f;
#pragma unroll
        for (int j = 0; j < N_CLS; j++) se += expf(z[j] - m);
        float v = z[t] - m - logf(se);
        g_outproto[(size_t)p * N_CLS + t] = v;
        if (write_out) out_proto_dst[(size_t)p * N_CLS + t] = v;
    }
}

// ---------------- out = log_softmax(x_rel @ out_proto) -----------------------
__device__ __forceinline__ void out_head_body(const float* __restrict__ xr_base,
                                              float* __restrict__ out) {
    __shared__ float ps[N_PROT * N_CLS];  // 32KB
    __shared__ float z[8][N_CLS];
    int t = threadIdx.x;
    for (int i = t; i < N_PROT * N_CLS; i += 128) ps[i] = g_outproto[i];
    __syncthreads();
    int g = t >> 4;
    int c = t & 15;
    int node = blockIdx.x * 8 + g;
    const float* xr = xr_base + (size_t)node * N_PROT;
    float s0 = 0.f, s1 = 0.f, s2 = 0.f, s3 = 0.f;
    for (int p = 0; p < N_PROT; p += 4) {
        s0 += xr[p + 0] * ps[(p + 0) * N_CLS + c];
        s1 += xr[p + 1] * ps[(p + 1) * N_CLS + c];
        s2 += xr[p + 2] * ps[(p + 2) * N_CLS + c];
        s3 += xr[p + 3] * ps[(p + 3) * N_CLS + c];
    }
    float s = (s0 + s1) + (s2 + s3);
    z[g][c] = s;
    __syncthreads();
    float m = z[g][0];
#pragma unroll
    for (int j = 1; j < N_CLS; j++) m = fmaxf(m, z[g][j]);
    float se = 0.f;
#pragma unroll
    for (int j = 0; j < N_CLS; j++) se += expf(z[g][j] - m);
    out[(size_t)node * N_CLS + c] = s - m - logf(se);
}

__global__ void k_out_head(const float* __restrict__ xrel, float* __restrict__ out) {
    out_head_body(xrel, out);
}
__global__ void k_out_head_scratch(float* __restrict__ out) {
    out_head_body(g_xrel_scratch, out);
}

// ---------------- launcher ----------------
extern "C" void kernel_launch(void* const* d_in, const int* in_sizes, int n_in,
                              void* d_out, int out_size) {
    const float* x    = (const float*)d_in[0];
    const int*   ei   = (const int*)d_in[1];     // int32
    const int*   prot = (const int*)d_in[2];     // int32

    int wbase = (in_sizes[3] <= 1) ? 4 : 3;
    const float* W0  = (const float*)d_in[wbase + 0];
    const float* b0  = (const float*)d_in[wbase + 1];
    const float* W1  = (const float*)d_in[wbase + 2];
    const float* b1  = (const float*)d_in[wbase + 3];
    const float* Wl1 = (const float*)d_in[wbase + 4];
    const float* bl1 = (const float*)d_in[wbase + 5];
    const float* Wl2 = (const float*)d_in[wbase + 6];
    const float* bl2 = (const float*)d_in[wbase + 7];

    const size_t SZ_OUT   = (size_t)N_NODES * N_CLS;
    const size_t SZ_XREL  = (size_t)N_NODES * N_PROT;
    const size_t SZ_PROTO = (size_t)N_PROT * N_CLS;

    float* out = (float*)d_out;
    bool full = ((size_t)out_size >= SZ_OUT + SZ_XREL + SZ_PROTO);
    float* xrel = nullptr;
    float* out_proto = nullptr;
    if (full) {
        xrel      = out + SZ_OUT;
        out_proto = xrel + SZ_XREL;
    }

    const int* src = ei;
    const int* dst = ei + N_EDGES;

    const int MB = (N_NODES + 127) / 128;   // 391
    dim3 g1(D_HID / 128, MB);
    dim3 g2(N_PROT / 128, MB);

    // launches 0-2: prep that k_dis needs
    k_zero_counts<<<(N_NODES + 255) / 256, 256>>>();
    k_count_deg<<<(N_EDGES + 255) / 256, 256>>>(dst);
    k_dis<<<(N_NODES + 255) / 256, 256>>>();
    // launch 3: gemm_xw0 (independent of graph prep) -> gets ncu-profiled
    k_gemm_xw0<<<g1, 256>>>(x, W0);
    // remaining graph prep
    k_scan_partial<<<N_TILES, SCAN_TILE>>>();
    k_scan_offsets<<<1, 32>>>();
    k_scan_final<<<N_TILES, SCAN_TILE>>>();
    k_fill_csr<<<(N_EDGES + 255) / 256, 256>>>(src, dst);

    // layer 0: h = relu(aggregate(xw) + b0)
    k_aggregate<<<N_NODES, 64>>>(b0, 1, 0);
    // layer 1: h = normalize(aggregate(h @ W1) + b1)   (rownorm fused)
    k_gemm_hw1<<<g1, 256>>>(W1);
    k_aggregate<<<N_NODES, 64>>>(b1, 0, 1);

    k_gather_anchors<<<N_PROT, 256>>>(prot);
    k_proto_head<<<N_PROT, 256>>>(Wl1, bl1, Wl2, bl2, out_proto, full ? 1 : 0);

    if (full) {
        k_gemm_xrel<<<g2, 256>>>(xrel);
        k_out_head<<<N_NODES / 8, 128>>>(xrel, out);
    } else {
        k_gemm_xrel_scratch<<<g2, 256>>>();
        k_out_head_scratch<<<N_NODES / 8, 128>>>(out);
    }
}

// round 13
// speedup vs baseline: 1.7621x; 1.3420x over previous
#include <cuda_runtime.h>
#include <cuda_bf16.h>
#include <math.h>
#include <stdint.h>

#define N_NODES 50000
#define N_EDGES 800000
#define D_IN    128
#define D_HID   256
#define N_CLS   16
#define N_PROT  512

#define SCAN_TILE 1024
#define N_TILES   ((N_NODES + SCAN_TILE - 1) / SCAN_TILE)   // 49

#define KC      32            // K chunk per smem stage
#define ASTR    40            // padded row stride in bf16 (32 + 8) -> 20 banks

// ---------------- scratch (device globals; no allocs allowed) ----------------
__device__ float g_dis[N_NODES];
__device__ int   g_indeg[N_NODES];
__device__ int   g_cursor[N_NODES];
__device__ int   g_rowptr[N_NODES + 1];
__device__ int   g_partial[N_TILES];
__device__ int   g_csr_src[N_EDGES];
__device__ float g_csr_w [N_EDGES];
__device__ float g_xw[(size_t)N_NODES * D_HID];
__device__ float g_h [(size_t)N_NODES * D_HID];
__device__ float g_xrel_scratch[(size_t)N_NODES * N_PROT];
__device__ float g_anchors [(size_t)N_PROT * D_HID];   // [P, H] = [N, K] for MMA B
__device__ float g_outproto[(size_t)N_PROT * N_CLS];

// ---------------- graph prep ----------------
__global__ void k_zero_counts() {
    int i = blockIdx.x * blockDim.x + threadIdx.x;
    if (i < N_NODES) { g_indeg[i] = 0; g_cursor[i] = 0; }
}

__global__ void k_count_deg(const int* __restrict__ dst) {
    int e = blockIdx.x * blockDim.x + threadIdx.x;
    if (e < N_EDGES) {
        int d = dst[e];
        if (d >= 0 && d < N_NODES) atomicAdd(&g_indeg[d], 1);
    }
}

__global__ void k_dis() {
    int i = blockIdx.x * blockDim.x + threadIdx.x;
    if (i < N_NODES) {
        float deg = (float)(g_indeg[i] + 1);
        g_dis[i] = 1.0f / sqrtf(deg);
    }
}

__global__ void k_scan_partial() {
    __shared__ int sh[SCAN_TILE];
    int b = blockIdx.x, t = threadIdx.x;
    int i = b * SCAN_TILE + t;
    sh[t] = (i < N_NODES) ? g_indeg[i] : 0;
    __syncthreads();
    for (int off = SCAN_TILE / 2; off > 0; off >>= 1) {
        if (t < off) sh[t] += sh[t + off];
        __syncthreads();
    }
    if (t == 0) g_partial[b] = sh[0];
}

__global__ void k_scan_offsets() {
    if (threadIdx.x == 0) {
        int acc = 0;
        for (int i = 0; i < N_TILES; i++) {
            int v = g_partial[i];
            g_partial[i] = acc;
            acc += v;
        }
    }
}

__global__ void k_scan_final() {
    __shared__ int sh[SCAN_TILE];
    int b = blockIdx.x, t = threadIdx.x;
    int i = b * SCAN_TILE + t;
    int v = (i < N_NODES) ? g_indeg[i] : 0;
    sh[t] = v;
    __syncthreads();
    for (int off = 1; off < SCAN_TILE; off <<= 1) {
        int u = (t >= off) ? sh[t - off] : 0;
        __syncthreads();
        sh[t] += u;
        __syncthreads();
    }
    if (i < N_NODES) g_rowptr[i + 1] = sh[t] + g_partial[b];
    if (b == 0 && t == 0) g_rowptr[0] = 0;
}

__global__ void k_fill_csr(const int* __restrict__ src,
                           const int* __restrict__ dst) {
    int e = blockIdx.x * blockDim.x + threadIdx.x;
    if (e < N_EDGES) {
        int d = dst[e];
        int s = src[e];
        if (d < 0 || d >= N_NODES || s < 0 || s >= N_NODES) return;
        int pos = atomicAdd(&g_cursor[d], 1);
        int idx = g_rowptr[d] + pos;
        if (idx >= 0 && idx < N_EDGES) {
            g_csr_src[idx] = s;
            g_csr_w[idx]   = g_dis[s] * g_dis[d];
        }
    }
}

// ============ HMMA split-bf16 GEMM: C[M,Ntot] = A[M,K] @ B ===================
// mma.sync.m16n8k16 row.col, fp32 acc. Split v = hi + lo (bf16 each):
//   D += Ahi*Bhi + Ahi*Blo + Alo*Bhi   (lo*lo dropped, ~2^-18 rel)
// A: [M,K] fp32. B: b_kn=1 -> Bsrc[K,Ntot] (transpose-on-load);
//                 b_kn=0 -> Bsrc[Ntot,K] (direct rows).
// Block 128x128, 256 thr = 8 warps (4m x 2n), warp tile 32x64, K chunk 32.

__device__ __forceinline__ void mma16816(float* d, const uint32_t* a, const uint32_t* b) {
    asm volatile(
        "mma.sync.aligned.m16n8k16.row.col.f32.bf16.bf16.f32 "
        "{%0,%1,%2,%3}, {%4,%5,%6,%7}, {%8,%9}, {%0,%1,%2,%3};\n"
        : "+f"(d[0]), "+f"(d[1]), "+f"(d[2]), "+f"(d[3])
        : "r"(a[0]), "r"(a[1]), "r"(a[2]), "r"(a[3]), "r"(b[0]), "r"(b[1]));
}

__device__ __forceinline__ void split_bf16(float v, __nv_bfloat16& h, __nv_bfloat16& l) {
    h = __float2bfloat16(v);
    l = __float2bfloat16(v - __bfloat162float(h));
}

__device__ __forceinline__ void hmma_gemm_body(const float* __restrict__ A,
                                               const float* __restrict__ Bsrc,
                                               float* __restrict__ C,
                                               int M, int Ntot, int K, int b_kn) {
    __shared__ __nv_bfloat16 sAhi[128 * ASTR], sAlo[128 * ASTR];
    __shared__ __nv_bfloat16 sBhi[128 * ASTR], sBlo[128 * ASTR];
    int t = threadIdx.x;
    int lane = t & 31, wid = t >> 5;
    int g = lane >> 2, tg = lane & 3;
    int wm = (wid & 3) * 32;        // warp row offset in tile
    int wn = (wid >> 2) * 64;       // warp col offset in tile
    int bm = blockIdx.y * 128;
    int bn = blockIdx.x * 128;

    float acc[2][8][4];
#pragma unroll
    for (int i = 0; i < 2; i++)
#pragma unroll
        for (int j = 0; j < 8; j++)
#pragma unroll
            for (int q = 0; q < 4; q++) acc[i][j][q] = 0.f;

    for (int kc = 0; kc < K; kc += KC) {
        // ---- A tile [128 x 32] fp32 -> hi/lo bf16 ----
        {
            int row = t >> 1, kh = (t & 1) * 16;
            int gm = bm + row;
            const float* src = &A[(size_t)gm * K + kc + kh];
#pragma unroll
            for (int q = 0; q < 8; q++) {
                float2 v = make_float2(0.f, 0.f);
                if (gm < M) v = *(const float2*)&src[2 * q];
                __nv_bfloat16 hx, lx, hy, ly;
                split_bf16(v.x, hx, lx);
                split_bf16(v.y, hy, ly);
                int o = row * ASTR + kh + 2 * q;
                *(__nv_bfloat162*)&sAhi[o] = __nv_bfloat162(hx, hy);
                *(__nv_bfloat162*)&sAlo[o] = __nv_bfloat162(lx, ly);
            }
        }
        // ---- B tile -> smem [n][k] hi/lo ----
        if (b_kn) {   // Bsrc[K,Ntot]: transpose on load (coalesced across n)
            int n = t & 127, kq = (t >> 7) * 16;
#pragma unroll
            for (int q = 0; q < 16; q++) {
                float v = Bsrc[(size_t)(kc + kq + q) * Ntot + bn + n];
                __nv_bfloat16 h, l;
                split_bf16(v, h, l);
                int o = n * ASTR + kq + q;
                sBhi[o] = h;
                sBlo[o] = l;
            }
        } else {      // Bsrc[Ntot,K]: direct rows (N_PROT/anchors case)
            int n = t >> 1, kh = (t & 1) * 16;
            const float* src = &Bsrc[(size_t)(bn + n) * K + kc + kh];
#pragma unroll
            for (int q = 0; q < 8; q++) {
                float2 v = *(const float2*)&src[2 * q];
                __nv_bfloat16 hx, lx, hy, ly;
                split_bf16(v.x, hx, lx);
                split_bf16(v.y, hy, ly);
                int o = n * ASTR + kh + 2 * q;
                *(__nv_bfloat162*)&sBhi[o] = __nv_bfloat162(hx, hy);
                *(__nv_bfloat162*)&sBlo[o] = __nv_bfloat162(lx, ly);
            }
        }
        __syncthreads();

        // ---- 2 k16 steps of MMAs ----
#pragma unroll
        for (int ks = 0; ks < KC; ks += 16) {
            uint32_t ahi[2][4], alo[2][4];
#pragma unroll
            for (int sm = 0; sm < 2; sm++) {
                int r = wm + sm * 16 + g;
                int c = ks + tg * 2;
                const __nv_bfloat16* ph = &sAhi[r * ASTR + c];
                ahi[sm][0] = *(const uint32_t*)ph;
                ahi[sm][1] = *(const uint32_t*)(ph + 8 * ASTR);
                ahi[sm][2] = *(const uint32_t*)(ph + 8);
                ahi[sm][3] = *(const uint32_t*)(ph + 8 * ASTR + 8);
                const __nv_bfloat16* pl = &sAlo[r * ASTR + c];
                alo[sm][0] = *(const uint32_t*)pl;
                alo[sm][1] = *(const uint32_t*)(pl + 8 * ASTR);
                alo[sm][2] = *(const uint32_t*)(pl + 8);
                alo[sm][3] = *(const uint32_t*)(pl + 8 * ASTR + 8);
            }
#pragma unroll
            for (int sn = 0; sn < 8; sn++) {
                int n = wn + sn * 8 + g;
                int c = ks + tg * 2;
                const __nv_bfloat16* ph = &sBhi[n * ASTR + c];
                uint32_t bh[2] = { *(const uint32_t*)ph, *(const uint32_t*)(ph + 8) };
                const __nv_bfloat16* pl = &sBlo[n * ASTR + c];
                uint32_t bl[2] = { *(const uint32_t*)pl, *(const uint32_t*)(pl + 8) };
#pragma unroll
                for (int sm = 0; sm < 2; sm++) {
                    mma16816(acc[sm][sn], ahi[sm], bh);
                    mma16816(acc[sm][sn], ahi[sm], bl);
                    mma16816(acc[sm][sn], alo[sm], bh);
                }
            }
        }
        __syncthreads();
    }

    // ---- epilogue ----
#pragma unroll
    for (int sm = 0; sm < 2; sm++) {
        int r0 = bm + wm + sm * 16 + g;
#pragma unroll
        for (int sn = 0; sn < 8; sn++) {
            int col = bn + wn + sn * 8 + tg * 2;
            if (r0 < M)
                *(float2*)&C[(size_t)r0 * Ntot + col] = make_float2(acc[sm][sn][0], acc[sm][sn][1]);
            if (r0 + 8 < M)
                *(float2*)&C[(size_t)(r0 + 8) * Ntot + col] = make_float2(acc[sm][sn][2], acc[sm][sn][3]);
        }
    }
}

__global__ void __launch_bounds__(256)
k_hmma_xw0(const float* __restrict__ x, const float* __restrict__ W0) {
    hmma_gemm_body(x, W0, g_xw, N_NODES, D_HID, D_IN, 1);
}
__global__ void __launch_bounds__(256)
k_hmma_hw1(const float* __restrict__ W1) {
    hmma_gemm_body(g_h, W1, g_xw, N_NODES, D_HID, D_HID, 1);
}
__global__ void __launch_bounds__(256)
k_hmma_xrel(float* __restrict__ xrel) {
    hmma_gemm_body(g_h, g_anchors, xrel, N_NODES, N_PROT, D_HID, 0);
}
__global__ void __launch_bounds__(256)
k_hmma_xrel_scratch() {
    hmma_gemm_body(g_h, g_anchors, g_xrel_scratch, N_NODES, N_PROT, D_HID, 0);
}

// ------- GCN aggregation v2: precomputed weights, x4 unroll, opt. rownorm ----
__global__ void k_aggregate(const float* __restrict__ bias, int do_relu, int do_norm) {
    int node = blockIdx.x;
    int t = threadIdx.x;  // 64 threads x float4 = 256 cols
    int beg = g_rowptr[node], end = g_rowptr[node + 1];
    const float4* xw4 = (const float4*)g_xw;
    float4 acc = make_float4(0.f, 0.f, 0.f, 0.f);

    int e = beg;
    for (; e + 4 <= end; e += 4) {
        int   s0 = g_csr_src[e],   s1 = g_csr_src[e+1];
        int   s2 = g_csr_src[e+2], s3 = g_csr_src[e+3];
        float w0 = g_csr_w[e],     w1 = g_csr_w[e+1];
        float w2 = g_csr_w[e+2],   w3 = g_csr_w[e+3];
        float4 v0 = xw4[(size_t)s0 * 64 + t];
        float4 v1 = xw4[(size_t)s1 * 64 + t];
        float4 v2 = xw4[(size_t)s2 * 64 + t];
        float4 v3 = xw4[(size_t)s3 * 64 + t];
        acc.x += w0*v0.x + w1*v1.x + w2*v2.x + w3*v3.x;
        acc.y += w0*v0.y + w1*v1.y + w2*v2.y + w3*v3.y;
        acc.z += w0*v0.z + w1*v1.z + w2*v2.z + w3*v3.z;
        acc.w += w0*v0.w + w1*v1.w + w2*v2.w + w3*v3.w;
    }
    for (; e < end; e++) {
        int s = g_csr_src[e];
        float w = g_csr_w[e];
        float4 v = xw4[(size_t)s * 64 + t];
        acc.x += w*v.x; acc.y += w*v.y; acc.z += w*v.z; acc.w += w*v.w;
    }
    {   // self loop
        float dn = g_dis[node];
        float w = dn * dn;
        float4 v = xw4[(size_t)node * 64 + t];
        acc.x += w*v.x; acc.y += w*v.y; acc.z += w*v.z; acc.w += w*v.w;
    }
    float4 bv = ((const float4*)bias)[t];
    acc.x += bv.x; acc.y += bv.y; acc.z += bv.z; acc.w += bv.w;
    if (do_relu) {
        acc.x = fmaxf(acc.x, 0.f); acc.y = fmaxf(acc.y, 0.f);
        acc.z = fmaxf(acc.z, 0.f); acc.w = fmaxf(acc.w, 0.f);
    }
    if (do_norm) {   // fused L2 row-normalize
        float s = acc.x*acc.x + acc.y*acc.y + acc.z*acc.z + acc.w*acc.w;
#pragma unroll
        for (int off = 16; off >= 1; off >>= 1)
            s += __shfl_xor_sync(0xFFFFFFFFu, s, off);
        __shared__ float ws[2];
        if ((t & 31) == 0) ws[t >> 5] = s;
        __syncthreads();
        s = ws[0] + ws[1];
        float r = 1.0f / sqrtf(s);
        acc.x *= r; acc.y *= r; acc.z *= r; acc.w *= r;
    }
    ((float4*)g_h)[(size_t)node * 64 + t] = acc;
}

// ---------------- anchor gather ----------------------------------------------
__global__ void k_gather_anchors(const int* __restrict__ prot) {
    int p = blockIdx.x;
    int t = threadIdx.x;  // 256
    int nl = prot[p];
    int node = (nl >= 0 && nl < N_NODES) ? nl : 0;
    g_anchors[(size_t)p * D_HID + t] = g_h[(size_t)node * D_HID + t];
}

// ---------------- prototype head: log_softmax(lin(anchors)) ------------------
__global__ void k_proto_head(const float* __restrict__ Wl1, const float* __restrict__ bl1,
                             const float* __restrict__ Wl2, const float* __restrict__ bl2,
                             float* __restrict__ out_proto_dst, int write_out) {
    int p = blockIdx.x;
    int t = threadIdx.x;  // 256
    __shared__ float a[D_HID];
    __shared__ float h1[D_HID];
    __shared__ float z[N_CLS];
    a[t] = g_anchors[(size_t)p * D_HID + t];
    __syncthreads();
    float s = bl1[t];
#pragma unroll 4
    for (int k = 0; k < D_HID; k++) s += a[k] * Wl1[(size_t)k * D_HID + t];
    h1[t] = fmaxf(s, 0.0f);
    __syncthreads();
    if (t < N_CLS) {
        float s2 = bl2[t];
#pragma unroll 4
        for (int k = 0; k < D_HID; k++) s2 += h1[k] * Wl2[(size_t)k * N_CLS + t];
        z[t] = s2;
    }
    __syncthreads();
    if (t < N_CLS) {
        float m = z[0];
#pragma unroll
        for (int j = 1; j < N_CLS; j++) m = fmaxf(m, z[j]);
        float se = 0.f;
#pragma unroll
        for (int j = 0; j < N_CLS; j++) se += expf(z[j] - m);
        float v = z[t] - m - logf(se);
        g_outproto[(size_t)p * N_CLS + t] = v;
        if (write_out) out_proto_dst[(size_t)p * N_CLS + t] = v;
    }
}

// ---------------- out = log_softmax(x_rel @ out_proto) -----------------------
__device__ __forceinline__ void out_head_body(const float* __restrict__ xr_base,
                                              float* __restrict__ out) {
    __shared__ float ps[N_PROT * N_CLS];  // 32KB
    __shared__ float z[8][N_CLS];
    int t = threadIdx.x;
    for (int i = t; i < N_PROT * N_CLS; i += 128) ps[i] = g_outproto[i];
    __syncthreads();
    int g = t >> 4;
    int c = t & 15;
    int node = blockIdx.x * 8 + g;
    const float* xr = xr_base + (size_t)node * N_PROT;
    float s0 = 0.f, s1 = 0.f, s2 = 0.f, s3 = 0.f;
    for (int p = 0; p < N_PROT; p += 4) {
        s0 += xr[p + 0] * ps[(p + 0) * N_CLS + c];
        s1 += xr[p + 1] * ps[(p + 1) * N_CLS + c];
        s2 += xr[p + 2] * ps[(p + 2) * N_CLS + c];
        s3 += xr[p + 3] * ps[(p + 3) * N_CLS + c];
    }
    float s = (s0 + s1) + (s2 + s3);
    z[g][c] = s;
    __syncthreads();
    float m = z[g][0];
#pragma unroll
    for (int j = 1; j < N_CLS; j++) m = fmaxf(m, z[g][j]);
    float se = 0.f;
#pragma unroll
    for (int j = 0; j < N_CLS; j++) se += expf(z[g][j] - m);
    out[(size_t)node * N_CLS + c] = s - m - logf(se);
}

__global__ void k_out_head(const float* __restrict__ xrel, float* __restrict__ out) {
    out_head_body(xrel, out);
}
__global__ void k_out_head_scratch(float* __restrict__ out) {
    out_head_body(g_xrel_scratch, out);
}

// ---------------- launcher ----------------
extern "C" void kernel_launch(void* const* d_in, const int* in_sizes, int n_in,
                              void* d_out, int out_size) {
    const float* x    = (const float*)d_in[0];
    const int*   ei   = (const int*)d_in[1];     // int32
    const int*   prot = (const int*)d_in[2];     // int32

    int wbase = (in_sizes[3] <= 1) ? 4 : 3;
    const float* W0  = (const float*)d_in[wbase + 0];
    const float* b0  = (const float*)d_in[wbase + 1];
    const float* W1  = (const float*)d_in[wbase + 2];
    const float* b1  = (const float*)d_in[wbase + 3];
    const float* Wl1 = (const float*)d_in[wbase + 4];
    const float* bl1 = (const float*)d_in[wbase + 5];
    const float* Wl2 = (const float*)d_in[wbase + 6];
    const float* bl2 = (const float*)d_in[wbase + 7];

    const size_t SZ_OUT   = (size_t)N_NODES * N_CLS;
    const size_t SZ_XREL  = (size_t)N_NODES * N_PROT;
    const size_t SZ_PROTO = (size_t)N_PROT * N_CLS;

    float* out = (float*)d_out;
    bool full = ((size_t)out_size >= SZ_OUT + SZ_XREL + SZ_PROTO);
    float* xrel = nullptr;
    float* out_proto = nullptr;
    if (full) {
        xrel      = out + SZ_OUT;
        out_proto = xrel + SZ_XREL;
    }

    const int* src = ei;
    const int* dst = ei + N_EDGES;

    const int MTILES = (N_NODES + 127) / 128;   // 391
    dim3 g1(D_HID / 128, MTILES);               // (2, 391)
    dim3 g2(N_PROT / 128, MTILES);              // (4, 391)

    // launches 0-2: prep that k_dis needs
    k_zero_counts<<<(N_NODES + 255) / 256, 256>>>();
    k_count_deg<<<(N_EDGES + 255) / 256, 256>>>(dst);
    k_dis<<<(N_NODES + 255) / 256, 256>>>();
    // launch 3: hmma gemm xw0 (independent of graph prep) -> ncu lands here
    k_hmma_xw0<<<g1, 256>>>(x, W0);
    // remaining graph prep
    k_scan_partial<<<N_TILES, SCAN_TILE>>>();
    k_scan_offsets<<<1, 32>>>();
    k_scan_final<<<N_TILES, SCAN_TILE>>>();
    k_fill_csr<<<(N_EDGES + 255) / 256, 256>>>(src, dst);

    // layer 0: h = relu(aggregate(xw) + b0)
    k_aggregate<<<N_NODES, 64>>>(b0, 1, 0);
    // layer 1: h = normalize(aggregate(h @ W1) + b1)
    k_hmma_hw1<<<g1, 256>>>(W1);
    k_aggregate<<<N_NODES, 64>>>(b1, 0, 1);

    k_gather_anchors<<<N_PROT, 256>>>(prot);
    k_proto_head<<<N_PROT, 256>>>(Wl1, bl1, Wl2, bl2, out_proto, full ? 1 : 0);

    if (full) {
        k_hmma_xrel<<<g2, 256>>>(xrel);
        k_out_head<<<N_NODES / 8, 128>>>(xrel, out);
    } else {
        k_hmma_xrel_scratch<<<g2, 256>>>();
        k_out_head_scratch<<<N_NODES / 8, 128>>>(out);
    }
}

// round 14
// speedup vs baseline: 1.9355x; 1.0984x over previous
#include <cuda_runtime.h>
#include <cuda_bf16.h>
#include <math.h>
#include <stdint.h>

#define N_NODES 50000
#define N_EDGES 800000
#define D_IN    128
#define D_HID   256
#define N_CLS   16
#define N_PROT  512

#define SCAN_TILE 1024
#define N_TILES   ((N_NODES + SCAN_TILE - 1) / SCAN_TILE)   // 49

#define KC   32               // K chunk per smem stage
#define FS   132              // fragment stride in 32-bit words (128 + 4 pad)

// ---------------- scratch (device globals; no allocs allowed) ----------------
__device__ float g_dis[N_NODES];
__device__ int   g_indeg[N_NODES];
__device__ int   g_cursor[N_NODES];
__device__ int   g_rowptr[N_NODES + 1];
__device__ int   g_partial[N_TILES];
__device__ int   g_csr_src[N_EDGES];
__device__ float g_csr_w [N_EDGES];
__device__ float g_xw[(size_t)N_NODES * D_HID];
__device__ float g_h [(size_t)N_NODES * D_HID];
__device__ float g_xrel_scratch[(size_t)N_NODES * N_PROT];
__device__ float g_anchors [(size_t)N_PROT * D_HID];   // [P, H] = [N, K] for MMA B
__device__ float g_outproto[(size_t)N_PROT * N_CLS];

// ---------------- graph prep ----------------
__global__ void k_zero_counts() {
    int i = blockIdx.x * blockDim.x + threadIdx.x;
    if (i < N_NODES) { g_indeg[i] = 0; g_cursor[i] = 0; }
}

__global__ void k_count_deg(const int* __restrict__ dst) {
    int e = blockIdx.x * blockDim.x + threadIdx.x;
    if (e < N_EDGES) {
        int d = dst[e];
        if (d >= 0 && d < N_NODES) atomicAdd(&g_indeg[d], 1);
    }
}

__global__ void k_dis() {
    int i = blockIdx.x * blockDim.x + threadIdx.x;
    if (i < N_NODES) {
        float deg = (float)(g_indeg[i] + 1);
        g_dis[i] = 1.0f / sqrtf(deg);
    }
}

__global__ void k_scan_partial() {
    __shared__ int sh[SCAN_TILE];
    int b = blockIdx.x, t = threadIdx.x;
    int i = b * SCAN_TILE + t;
    sh[t] = (i < N_NODES) ? g_indeg[i] : 0;
    __syncthreads();
    for (int off = SCAN_TILE / 2; off > 0; off >>= 1) {
        if (t < off) sh[t] += sh[t + off];
        __syncthreads();
    }
    if (t == 0) g_partial[b] = sh[0];
}

__global__ void k_scan_offsets() {
    if (threadIdx.x == 0) {
        int acc = 0;
        for (int i = 0; i < N_TILES; i++) {
            int v = g_partial[i];
            g_partial[i] = acc;
            acc += v;
        }
    }
}

__global__ void k_scan_final() {
    __shared__ int sh[SCAN_TILE];
    int b = blockIdx.x, t = threadIdx.x;
    int i = b * SCAN_TILE + t;
    int v = (i < N_NODES) ? g_indeg[i] : 0;
    sh[t] = v;
    __syncthreads();
    for (int off = 1; off < SCAN_TILE; off <<= 1) {
        int u = (t >= off) ? sh[t - off] : 0;
        __syncthreads();
        sh[t] += u;
        __syncthreads();
    }
    if (i < N_NODES) g_rowptr[i + 1] = sh[t] + g_partial[b];
    if (b == 0 && t == 0) g_rowptr[0] = 0;
}

__global__ void k_fill_csr(const int* __restrict__ src,
                           const int* __restrict__ dst) {
    int e = blockIdx.x * blockDim.x + threadIdx.x;
    if (e < N_EDGES) {
        int d = dst[e];
        int s = src[e];
        if (d < 0 || d >= N_NODES || s < 0 || s >= N_NODES) return;
        int pos = atomicAdd(&g_cursor[d], 1);
        int idx = g_rowptr[d] + pos;
        if (idx >= 0 && idx < N_EDGES) {
            g_csr_src[idx] = s;
            g_csr_w[idx]   = g_dis[s] * g_dis[d];
        }
    }
}

// ============ HMMA split-bf16 GEMM, fragment-staged smem =====================
// mma.sync.m16n8k16 row.col fp32 acc; D += Ahi*Bhi + Ahi*Blo + Alo*Bhi.
// smem holds tiles in FRAGMENT layout: each (fragment, lane) owns 4 consecutive
// words -> mainloop fragment loads are LDS.128 (12 per k16 per warp).
// XOR line swizzle (line ^= line>>3) + FS=132 padding -> conflict-free both ways.
// A frag q order: [a0=(g,klo) a1=(g+8,klo) a2=(g,khi) a3=(g+8,khi)]
// B frag pair:    [b0_sn_even b1_sn_even b0_sn_odd b1_sn_odd]

__device__ __forceinline__ void mma16816(float* d, const uint32_t* a, const uint32_t* b) {
    asm volatile(
        "mma.sync.aligned.m16n8k16.row.col.f32.bf16.bf16.f32 "
        "{%0,%1,%2,%3}, {%4,%5,%6,%7}, {%8,%9}, {%0,%1,%2,%3};\n"
        : "+f"(d[0]), "+f"(d[1]), "+f"(d[2]), "+f"(d[3])
        : "r"(a[0]), "r"(a[1]), "r"(a[2]), "r"(a[3]), "r"(b[0]), "r"(b[1]));
}

__device__ __forceinline__ void split2(float x, float y, uint32_t& hi, uint32_t& lo) {
    __nv_bfloat16 hx = __float2bfloat16(x);
    __nv_bfloat16 hy = __float2bfloat16(y);
    __nv_bfloat16 lx = __float2bfloat16(x - __bfloat162float(hx));
    __nv_bfloat16 ly = __float2bfloat16(y - __bfloat162float(hy));
    __nv_bfloat162 ph(hx, hy), pl(lx, ly);
    hi = *(uint32_t*)&ph;
    lo = *(uint32_t*)&pl;
}

__device__ __forceinline__ void hmma_gemm_body(const float* __restrict__ A,
                                               const float* __restrict__ Bsrc,
                                               float* __restrict__ C,
                                               int M, int Ntot, int K, int b_kn) {
    // 16 fragments each: A = tile16(8) x k16(2); B = band(2) x k16(2) x pair(4)
    __shared__ uint32_t sAhi[16 * FS], sAlo[16 * FS];
    __shared__ uint32_t sBhi[16 * FS], sBlo[16 * FS];
    int t = threadIdx.x;
    int lane = t & 31, wid = t >> 5;
    int g = lane >> 2, tg = lane & 3;
    int lsw = lane ^ (lane >> 3);               // swizzled line for this lane
    int wmi = (wid & 3);                        // warp m index (rows wmi*32..+31)
    int band = wid >> 2;                        // warp n band (0 or 1): cols band*64..+63
    int bm = blockIdx.y * 128;
    int bn = blockIdx.x * 128;

    float acc[2][8][4];
#pragma unroll
    for (int i = 0; i < 2; i++)
#pragma unroll
        for (int j = 0; j < 8; j++)
#pragma unroll
            for (int q = 0; q < 4; q++) acc[i][j][q] = 0.f;

    for (int kc = 0; kc < K; kc += KC) {
        // ---- stage A [128 x 32] fp32 -> hi/lo fragments ----
        {
            int row = t >> 1;
            int khalf = t & 1;                  // kw = khalf*8 + q2
            int gm = bm + row;
            const float* src = &A[(size_t)gm * K + kc + khalf * 16];
            int tile16 = row >> 4;
            int rbit = (row >> 3) & 1;
            int lbase = (row & 7) * 4;
#pragma unroll
            for (int q2 = 0; q2 < 8; q2++) {
                float2 v = make_float2(0.f, 0.f);
                if (gm < M) v = *(const float2*)&src[2 * q2];
                uint32_t whi, wlo;
                split2(v.x, v.y, whi, wlo);
                int kw  = khalf * 8 + q2;
                int k16 = kw >> 3, kw8 = kw & 7;
                int line = lbase + (kw8 & 3);
                int ls = line ^ (line >> 3);
                int q  = ((kw8 >> 2) << 1) + rbit;
                int o  = (tile16 * 2 + k16) * FS + ls * 4 + q;
                sAhi[o] = whi;
                sAlo[o] = wlo;
            }
        }
        // ---- stage B [128n x 32k] -> hi/lo fragments ----
        if (b_kn) {   // Bsrc[K,Ntot], transpose on load (coalesced over n)
            int n = t & 127;
            int kh = t >> 7;                    // 0 or 1
            int bandw = n >> 6, nb = n & 63;
            int sn = nb >> 3, pair = sn >> 1, inner = sn & 1;
            int lbase = (nb & 7) * 4;
#pragma unroll
            for (int q2 = 0; q2 < 8; q2++) {
                int kw = kh * 8 + q2;
                int k0 = kc + 2 * kw;
                float vx = Bsrc[(size_t)k0 * Ntot + bn + n];
                float vy = Bsrc[(size_t)(k0 + 1) * Ntot + bn + n];
                uint32_t whi, wlo;
                split2(vx, vy, whi, wlo);
                int k16 = kw >> 3, kw8 = kw & 7;
                int line = lbase + (kw8 & 3);
                int ls = line ^ (line >> 3);
                int q  = inner * 2 + (kw8 >> 2);
                int o  = ((bandw * 2 + k16) * 4 + pair) * FS + ls * 4 + q;
                sBhi[o] = whi;
                sBlo[o] = wlo;
            }
        } else {      // Bsrc[Ntot,K] direct rows
            int n = t >> 1;
            int khalf = t & 1;
            const float* src = &Bsrc[(size_t)(bn + n) * K + kc + khalf * 16];
            int bandw = n >> 6, nb = n & 63;
            int sn = nb >> 3, pair = sn >> 1, inner = sn & 1;
            int lbase = (nb & 7) * 4;
#pragma unroll
            for (int q2 = 0; q2 < 8; q2++) {
                float2 v = *(const float2*)&src[2 * q2];
                uint32_t whi, wlo;
                split2(v.x, v.y, whi, wlo);
                int kw  = khalf * 8 + q2;
                int k16 = kw >> 3, kw8 = kw & 7;
                int line = lbase + (kw8 & 3);
                int ls = line ^ (line >> 3);
                int q  = inner * 2 + (kw8 >> 2);
                int o  = ((bandw * 2 + k16) * 4 + pair) * FS + ls * 4 + q;
                sBhi[o] = whi;
                sBlo[o] = wlo;
            }
        }
        __syncthreads();

        // ---- MMA: 2 k16 steps ----
#pragma unroll
        for (int k16 = 0; k16 < 2; k16++) {
            uint32_t ahi[2][4], alo[2][4];
#pragma unroll
            for (int sm = 0; sm < 2; sm++) {
                int frag = (wmi * 2 + sm) * 2 + k16;
                uint4 vh = *(const uint4*)&sAhi[frag * FS + lsw * 4];
                ahi[sm][0] = vh.x; ahi[sm][1] = vh.y; ahi[sm][2] = vh.z; ahi[sm][3] = vh.w;
                uint4 vl = *(const uint4*)&sAlo[frag * FS + lsw * 4];
                alo[sm][0] = vl.x; alo[sm][1] = vl.y; alo[sm][2] = vl.z; alo[sm][3] = vl.w;
            }
#pragma unroll
            for (int pair = 0; pair < 4; pair++) {
                int frag = ((band * 2 + k16) * 4 + pair) * FS + lsw * 4;
                uint4 vbh = *(const uint4*)&sBhi[frag];
                uint4 vbl = *(const uint4*)&sBlo[frag];
                uint32_t bhe[2] = { vbh.x, vbh.y }, bho[2] = { vbh.z, vbh.w };
                uint32_t ble[2] = { vbl.x, vbl.y }, blo2[2] = { vbl.z, vbl.w };
#pragma unroll
                for (int sm = 0; sm < 2; sm++) {
                    mma16816(acc[sm][2 * pair],     ahi[sm], bhe);
                    mma16816(acc[sm][2 * pair],     ahi[sm], ble);
                    mma16816(acc[sm][2 * pair],     alo[sm], bhe);
                    mma16816(acc[sm][2 * pair + 1], ahi[sm], bho);
                    mma16816(acc[sm][2 * pair + 1], ahi[sm], blo2);
                    mma16816(acc[sm][2 * pair + 1], alo[sm], bho);
                }
            }
        }
        __syncthreads();
    }

    // ---- epilogue ----
#pragma unroll
    for (int sm = 0; sm < 2; sm++) {
        int r0 = bm + wmi * 32 + sm * 16 + g;
#pragma unroll
        for (int sn = 0; sn < 8; sn++) {
            int col = bn + band * 64 + sn * 8 + tg * 2;
            if (r0 < M)
                *(float2*)&C[(size_t)r0 * Ntot + col] = make_float2(acc[sm][sn][0], acc[sm][sn][1]);
            if (r0 + 8 < M)
                *(float2*)&C[(size_t)(r0 + 8) * Ntot + col] = make_float2(acc[sm][sn][2], acc[sm][sn][3]);
        }
    }
}

__global__ void __launch_bounds__(256)
k_hmma_xw0(const float* __restrict__ x, const float* __restrict__ W0) {
    hmma_gemm_body(x, W0, g_xw, N_NODES, D_HID, D_IN, 1);
}
__global__ void __launch_bounds__(256)
k_hmma_hw1(const float* __restrict__ W1) {
    hmma_gemm_body(g_h, W1, g_xw, N_NODES, D_HID, D_HID, 1);
}
__global__ void __launch_bounds__(256)
k_hmma_xrel(float* __restrict__ xrel) {
    hmma_gemm_body(g_h, g_anchors, xrel, N_NODES, N_PROT, D_HID, 0);
}
__global__ void __launch_bounds__(256)
k_hmma_xrel_scratch() {
    hmma_gemm_body(g_h, g_anchors, g_xrel_scratch, N_NODES, N_PROT, D_HID, 0);
}

// ------- GCN aggregation v2: precomputed weights, x4 unroll, opt. rownorm ----
__global__ void k_aggregate(const float* __restrict__ bias, int do_relu, int do_norm) {
    int node = blockIdx.x;
    int t = threadIdx.x;  // 64 threads x float4 = 256 cols
    int beg = g_rowptr[node], end = g_rowptr[node + 1];
    const float4* xw4 = (const float4*)g_xw;
    float4 acc = make_float4(0.f, 0.f, 0.f, 0.f);

    int e = beg;
    for (; e + 4 <= end; e += 4) {
        int   s0 = g_csr_src[e],   s1 = g_csr_src[e+1];
        int   s2 = g_csr_src[e+2], s3 = g_csr_src[e+3];
        float w0 = g_csr_w[e],     w1 = g_csr_w[e+1];
        float w2 = g_csr_w[e+2],   w3 = g_csr_w[e+3];
        float4 v0 = xw4[(size_t)s0 * 64 + t];
        float4 v1 = xw4[(size_t)s1 * 64 + t];
        float4 v2 = xw4[(size_t)s2 * 64 + t];
        float4 v3 = xw4[(size_t)s3 * 64 + t];
        acc.x += w0*v0.x + w1*v1.x + w2*v2.x + w3*v3.x;
        acc.y += w0*v0.y + w1*v1.y + w2*v2.y + w3*v3.y;
        acc.z += w0*v0.z + w1*v1.z + w2*v2.z + w3*v3.z;
        acc.w += w0*v0.w + w1*v1.w + w2*v2.w + w3*v3.w;
    }
    for (; e < end; e++) {
        int s = g_csr_src[e];
        float w = g_csr_w[e];
        float4 v = xw4[(size_t)s * 64 + t];
        acc.x += w*v.x; acc.y += w*v.y; acc.z += w*v.z; acc.w += w*v.w;
    }
    {   // self loop
        float dn = g_dis[node];
        float w = dn * dn;
        float4 v = xw4[(size_t)node * 64 + t];
        acc.x += w*v.x; acc.y += w*v.y; acc.z += w*v.z; acc.w += w*v.w;
    }
    float4 bv = ((const float4*)bias)[t];
    acc.x += bv.x; acc.y += bv.y; acc.z += bv.z; acc.w += bv.w;
    if (do_relu) {
        acc.x = fmaxf(acc.x, 0.f); acc.y = fmaxf(acc.y, 0.f);
        acc.z = fmaxf(acc.z, 0.f); acc.w = fmaxf(acc.w, 0.f);
    }
    if (do_norm) {   // fused L2 row-normalize
        float s = acc.x*acc.x + acc.y*acc.y + acc.z*acc.z + acc.w*acc.w;
#pragma unroll
        for (int off = 16; off >= 1; off >>= 1)
            s += __shfl_xor_sync(0xFFFFFFFFu, s, off);
        __shared__ float ws[2];
        if ((t & 31) == 0) ws[t >> 5] = s;
        __syncthreads();
        s = ws[0] + ws[1];
        float r = 1.0f / sqrtf(s);
        acc.x *= r; acc.y *= r; acc.z *= r; acc.w *= r;
    }
    ((float4*)g_h)[(size_t)node * 64 + t] = acc;
}

// ---------------- anchor gather ----------------------------------------------
__global__ void k_gather_anchors(const int* __restrict__ prot) {
    int p = blockIdx.x;
    int t = threadIdx.x;  // 256
    int nl = prot[p];
    int node = (nl >= 0 && nl < N_NODES) ? nl : 0;
    g_anchors[(size_t)p * D_HID + t] = g_h[(size_t)node * D_HID + t];
}

// ---------------- prototype head: log_softmax(lin(anchors)) ------------------
__global__ void k_proto_head(const float* __restrict__ Wl1, const float* __restrict__ bl1,
                             const float* __restrict__ Wl2, const float* __restrict__ bl2,
                             float* __restrict__ out_proto_dst, int write_out) {
    int p = blockIdx.x;
    int t = threadIdx.x;  // 256
    __shared__ float a[D_HID];
    __shared__ float h1[D_HID];
    __shared__ float z[N_CLS];
    a[t] = g_anchors[(size_t)p * D_HID + t];
    __syncthreads();
    float s = bl1[t];
#pragma unroll 4
    for (int k = 0; k < D_HID; k++) s += a[k] * Wl1[(size_t)k * D_HID + t];
    h1[t] = fmaxf(s, 0.0f);
    __syncthreads();
    if (t < N_CLS) {
        float s2 = bl2[t];
#pragma unroll 4
        for (int k = 0; k < D_HID; k++) s2 += h1[k] * Wl2[(size_t)k * N_CLS + t];
        z[t] = s2;
    }
    __syncthreads();
    if (t < N_CLS) {
        float m = z[0];
#pragma unroll
        for (int j = 1; j < N_CLS; j++) m = fmaxf(m, z[j]);
        float se = 0.f;
#pragma unroll
        for (int j = 0; j < N_CLS; j++) se += expf(z[j] - m);
        float v = z[t] - m - logf(se);
        g_outproto[(size_t)p * N_CLS + t] = v;
        if (write_out) out_proto_dst[(size_t)p * N_CLS + t] = v;
    }
}

// ---------------- out = log_softmax(x_rel @ out_proto) -----------------------
__device__ __forceinline__ void out_head_body(const float* __restrict__ xr_base,
                                              float* __restrict__ out) {
    __shared__ float ps[N_PROT * N_CLS];  // 32KB
    __shared__ float z[8][N_CLS];
    int t = threadIdx.x;
    for (int i = t; i < N_PROT * N_CLS; i += 128) ps[i] = g_outproto[i];
    __syncthreads();
    int g = t >> 4;
    int c = t & 15;
    int node = blockIdx.x * 8 + g;
    const float* xr = xr_base + (size_t)node * N_PROT;
    float s0 = 0.f, s1 = 0.f, s2 = 0.f, s3 = 0.f;
    for (int p = 0; p < N_PROT; p += 4) {
        s0 += xr[p + 0] * ps[(p + 0) * N_CLS + c];
        s1 += xr[p + 1] * ps[(p + 1) * N_CLS + c];
        s2 += xr[p + 2] * ps[(p + 2) * N_CLS + c];
        s3 += xr[p + 3] * ps[(p + 3) * N_CLS + c];
    }
    float s = (s0 + s1) + (s2 + s3);
    z[g][c] = s;
    __syncthreads();
    float m = z[g][0];
#pragma unroll
    for (int j = 1; j < N_CLS; j++) m = fmaxf(m, z[g][j]);
    float se = 0.f;
#pragma unroll
    for (int j = 0; j < N_CLS; j++) se += expf(z[g][j] - m);
    out[(size_t)node * N_CLS + c] = s - m - logf(se);
}

__global__ void k_out_head(const float* __restrict__ xrel, float* __restrict__ out) {
    out_head_body(xrel, out);
}
__global__ void k_out_head_scratch(float* __restrict__ out) {
    out_head_body(g_xrel_scratch, out);
}

// ---------------- launcher ----------------
extern "C" void kernel_launch(void* const* d_in, const int* in_sizes, int n_in,
                              void* d_out, int out_size) {
    const float* x    = (const float*)d_in[0];
    const int*   ei   = (const int*)d_in[1];     // int32
    const int*   prot = (const int*)d_in[2];     // int32

    int wbase = (in_sizes[3] <= 1) ? 4 : 3;
    const float* W0  = (const float*)d_in[wbase + 0];
    const float* b0  = (const float*)d_in[wbase + 1];
    const float* W1  = (const float*)d_in[wbase + 2];
    const float* b1  = (const float*)d_in[wbase + 3];
    const float* Wl1 = (const float*)d_in[wbase + 4];
    const float* bl1 = (const float*)d_in[wbase + 5];
    const float* Wl2 = (const float*)d_in[wbase + 6];
    const float* bl2 = (const float*)d_in[wbase + 7];

    const size_t SZ_OUT   = (size_t)N_NODES * N_CLS;
    const size_t SZ_XREL  = (size_t)N_NODES * N_PROT;
    const size_t SZ_PROTO = (size_t)N_PROT * N_CLS;

    float* out = (float*)d_out;
    bool full = ((size_t)out_size >= SZ_OUT + SZ_XREL + SZ_PROTO);
    float* xrel = nullptr;
    float* out_proto = nullptr;
    if (full) {
        xrel      = out + SZ_OUT;
        out_proto = xrel + SZ_XREL;
    }

    const int* src = ei;
    const int* dst = ei + N_EDGES;

    const int MTILES = (N_NODES + 127) / 128;   // 391
    dim3 g1(D_HID / 128, MTILES);               // (2, 391)
    dim3 g2(N_PROT / 128, MTILES);              // (4, 391)

    // launches 0-2: prep that k_dis needs
    k_zero_counts<<<(N_NODES + 255) / 256, 256>>>();
    k_count_deg<<<(N_EDGES + 255) / 256, 256>>>(dst);
    k_dis<<<(N_NODES + 255) / 256, 256>>>();
    // launch 3: hmma gemm xw0 (independent of graph prep) -> ncu lands here
    k_hmma_xw0<<<g1, 256>>>(x, W0);
    // remaining graph prep
    k_scan_partial<<<N_TILES, SCAN_TILE>>>();
    k_scan_offsets<<<1, 32>>>();
    k_scan_final<<<N_TILES, SCAN_TILE>>>();
    k_fill_csr<<<(N_EDGES + 255) / 256, 256>>>(src, dst);

    // layer 0: h = relu(aggregate(xw) + b0)
    k_aggregate<<<N_NODES, 64>>>(b0, 1, 0);
    // layer 1: h = normalize(aggregate(h @ W1) + b1)
    k_hmma_hw1<<<g1, 256>>>(W1);
    k_aggregate<<<N_NODES, 64>>>(b1, 0, 1);

    k_gather_anchors<<<N_PROT, 256>>>(prot);
    k_proto_head<<<N_PROT, 256>>>(Wl1, bl1, Wl2, bl2, out_proto, full ? 1 : 0);

    if (full) {
        k_hmma_xrel<<<g2, 256>>>(xrel);
        k_out_head<<<N_NODES / 8, 128>>>(xrel, out);
    } else {
        k_hmma_xrel_scratch<<<g2, 256>>>();
        k_out_head_scratch<<<N_NODES / 8, 128>>>(out);
    }
}

// round 15
// speedup vs baseline: 2.0006x; 1.0336x over previous
#include <cuda_runtime.h>
#include <cuda_bf16.h>
#include <math.h>
#include <stdint.h>

#define N_NODES 50000
#define N_EDGES 800000
#define D_IN    128
#define D_HID   256
#define N_CLS   16
#define N_PROT  512

#define SCAN_TILE 1024
#define N_TILES   ((N_NODES + SCAN_TILE - 1) / SCAN_TILE)   // 49

#define KC   32               // K chunk per smem stage
#define FS   132              // fragment stride in 32-bit words (128 + 4 pad)

// ---------------- scratch (device globals; no allocs allowed) ----------------
__device__ float g_dis[N_NODES];
__device__ int   g_indeg[N_NODES];
__device__ int   g_cursor[N_NODES];
__device__ int   g_rowptr[N_NODES + 1];
__device__ int   g_partial[N_TILES];
__device__ int   g_csr_src[N_EDGES];
__device__ float g_csr_w [N_EDGES];
__device__ float g_xw[(size_t)N_NODES * D_HID];           // GEMM out (fp32, pre-agg)
__device__ float g_xrel_scratch[(size_t)N_NODES * N_PROT];
__device__ float g_outproto[(size_t)N_PROT * N_CLS];
// bf16 hi/lo planes (packed pairs: word w = bf16x2(elem 2w, 2w+1))
__device__ uint32_t g_xhi[(size_t)N_NODES * (D_IN / 2)];
__device__ uint32_t g_xlo[(size_t)N_NODES * (D_IN / 2)];
__device__ uint32_t g_hhi[(size_t)N_NODES * (D_HID / 2)];
__device__ uint32_t g_hlo[(size_t)N_NODES * (D_HID / 2)];
__device__ uint32_t g_w0hi[256 * (D_IN / 2)];             // W0^T [256][64]
__device__ uint32_t g_w0lo[256 * (D_IN / 2)];
__device__ uint32_t g_w1hi[256 * (D_HID / 2)];            // W1^T [256][128]
__device__ uint32_t g_w1lo[256 * (D_HID / 2)];
__device__ uint32_t g_anchhi[N_PROT * (D_HID / 2)];
__device__ uint32_t g_anchlo[N_PROT * (D_HID / 2)];

// ---------------- helpers ----------------
__device__ __forceinline__ void split2(float x, float y, uint32_t& hi, uint32_t& lo) {
    __nv_bfloat16 hx = __float2bfloat16(x);
    __nv_bfloat16 hy = __float2bfloat16(y);
    __nv_bfloat16 lx = __float2bfloat16(x - __bfloat162float(hx));
    __nv_bfloat16 ly = __float2bfloat16(y - __bfloat162float(hy));
    __nv_bfloat162 ph(hx, hy), pl(lx, ly);
    hi = *(uint32_t*)&ph;
    lo = *(uint32_t*)&pl;
}

__device__ __forceinline__ void mma16816(float* d, const uint32_t* a, const uint32_t* b) {
    asm volatile(
        "mma.sync.aligned.m16n8k16.row.col.f32.bf16.bf16.f32 "
        "{%0,%1,%2,%3}, {%4,%5,%6,%7}, {%8,%9}, {%0,%1,%2,%3};\n"
        : "+f"(d[0]), "+f"(d[1]), "+f"(d[2]), "+f"(d[3])
        : "r"(a[0]), "r"(a[1]), "r"(a[2]), "r"(a[3]), "r"(b[0]), "r"(b[1]));
}

// ---------------- preconversion kernels ----------------
__global__ void k_split_x(const float* __restrict__ x) {
    size_t i = (size_t)blockIdx.x * blockDim.x + threadIdx.x;   // word index
    if (i < (size_t)N_NODES * (D_IN / 2)) {
        float2 v = ((const float2*)x)[i];
        split2(v.x, v.y, g_xhi[i], g_xlo[i]);
    }
}

// W [K][N] fp32 -> W^T hi/lo planes [N][K/2]
__global__ void k_split_w(const float* __restrict__ W0, const float* __restrict__ W1) {
    int i = blockIdx.x * blockDim.x + threadIdx.x;
    const int W0_WORDS = 256 * (D_IN / 2);      // 16384
    const int W1_WORDS = 256 * (D_HID / 2);     // 32768
    if (i < W0_WORDS) {
        int n = i / (D_IN / 2), kw = i % (D_IN / 2);
        float a = W0[(size_t)(2 * kw) * D_HID + n];
        float b = W0[(size_t)(2 * kw + 1) * D_HID + n];
        split2(a, b, g_w0hi[i], g_w0lo[i]);
    } else if (i < W0_WORDS + W1_WORDS) {
        int j = i - W0_WORDS;
        int n = j / (D_HID / 2), kw = j % (D_HID / 2);
        float a = W1[(size_t)(2 * kw) * D_HID + n];
        float b = W1[(size_t)(2 * kw + 1) * D_HID + n];
        split2(a, b, g_w1hi[j], g_w1lo[j]);
    }
}

// ---------------- graph prep ----------------
__global__ void k_zero_counts() {
    int i = blockIdx.x * blockDim.x + threadIdx.x;
    if (i < N_NODES) { g_indeg[i] = 0; g_cursor[i] = 0; }
}

__global__ void k_count_deg(const int* __restrict__ dst) {
    int e = blockIdx.x * blockDim.x + threadIdx.x;
    if (e < N_EDGES) {
        int d = dst[e];
        if (d >= 0 && d < N_NODES) atomicAdd(&g_indeg[d], 1);
    }
}

__global__ void k_dis() {
    int i = blockIdx.x * blockDim.x + threadIdx.x;
    if (i < N_NODES) {
        float deg = (float)(g_indeg[i] + 1);
        g_dis[i] = 1.0f / sqrtf(deg);
    }
}

__global__ void k_scan_partial() {
    __shared__ int sh[SCAN_TILE];
    int b = blockIdx.x, t = threadIdx.x;
    int i = b * SCAN_TILE + t;
    sh[t] = (i < N_NODES) ? g_indeg[i] : 0;
    __syncthreads();
    for (int off = SCAN_TILE / 2; off > 0; off >>= 1) {
        if (t < off) sh[t] += sh[t + off];
        __syncthreads();
    }
    if (t == 0) g_partial[b] = sh[0];
}

__global__ void k_scan_offsets() {
    if (threadIdx.x == 0) {
        int acc = 0;
        for (int i = 0; i < N_TILES; i++) {
            int v = g_partial[i];
            g_partial[i] = acc;
            acc += v;
        }
    }
}

__global__ void k_scan_final() {
    __shared__ int sh[SCAN_TILE];
    int b = blockIdx.x, t = threadIdx.x;
    int i = b * SCAN_TILE + t;
    int v = (i < N_NODES) ? g_indeg[i] : 0;
    sh[t] = v;
    __syncthreads();
    for (int off = 1; off < SCAN_TILE; off <<= 1) {
        int u = (t >= off) ? sh[t - off] : 0;
        __syncthreads();
        sh[t] += u;
        __syncthreads();
    }
    if (i < N_NODES) g_rowptr[i + 1] = sh[t] + g_partial[b];
    if (b == 0 && t == 0) g_rowptr[0] = 0;
}

__global__ void k_fill_csr(const int* __restrict__ src,
                           const int* __restrict__ dst) {
    int e = blockIdx.x * blockDim.x + threadIdx.x;
    if (e < N_EDGES) {
        int d = dst[e];
        int s = src[e];
        if (d < 0 || d >= N_NODES || s < 0 || s >= N_NODES) return;
        int pos = atomicAdd(&g_cursor[d], 1);
        int idx = g_rowptr[d] + pos;
        if (idx >= 0 && idx < N_EDGES) {
            g_csr_src[idx] = s;
            g_csr_w[idx]   = g_dis[s] * g_dis[d];
        }
    }
}

// ============ HMMA split-bf16 GEMM, plane inputs, fragment-staged smem =======
// Inputs already bf16 hi/lo planes [rows][K/2 words]. D += Ahi*Bhi+Ahi*Blo+Alo*Bhi.
// Fragment smem layout identical to R14 (LDS.128 frag loads, XOR line swizzle).
__device__ __forceinline__ void hmma_gemm_body(const uint32_t* __restrict__ Ahi,
                                               const uint32_t* __restrict__ Alo,
                                               const uint32_t* __restrict__ Bhi,
                                               const uint32_t* __restrict__ Blo,
                                               float* __restrict__ C,
                                               int M, int Ntot, int K) {
    __shared__ uint32_t sAhi[16 * FS], sAlo[16 * FS];
    __shared__ uint32_t sBhi[16 * FS], sBlo[16 * FS];
    int t = threadIdx.x;
    int lane = t & 31, wid = t >> 5;
    int g = lane >> 2, tg = lane & 3;
    int lsw = lane ^ (lane >> 3);
    int wmi = (wid & 3);
    int band = wid >> 2;
    int bm = blockIdx.y * 128;
    int bn = blockIdx.x * 128;
    int Kw = K >> 1;

    float acc[2][8][4];
#pragma unroll
    for (int i = 0; i < 2; i++)
#pragma unroll
        for (int j = 0; j < 8; j++)
#pragma unroll
            for (int q = 0; q < 4; q++) acc[i][j][q] = 0.f;

    for (int kc = 0; kc < K; kc += KC) {
        // ---- stage A [128 rows x 16 words] ----
        {
            int row = t >> 1, khalf = t & 1;
            int gm = bm + row;
            size_t base = (size_t)gm * Kw + (kc >> 1) + khalf * 8;
            uint4 vh0 = make_uint4(0,0,0,0), vh1 = vh0, vl0 = vh0, vl1 = vh0;
            if (gm < M) {
                vh0 = *(const uint4*)&Ahi[base];
                vh1 = *(const uint4*)&Ahi[base + 4];
                vl0 = *(const uint4*)&Alo[base];
                vl1 = *(const uint4*)&Alo[base + 4];
            }
            uint32_t wh[8] = {vh0.x, vh0.y, vh0.z, vh0.w, vh1.x, vh1.y, vh1.z, vh1.w};
            uint32_t wl[8] = {vl0.x, vl0.y, vl0.z, vl0.w, vl1.x, vl1.y, vl1.z, vl1.w};
            int tile16 = row >> 4, rbit = (row >> 3) & 1, lbase = (row & 7) * 4;
#pragma unroll
            for (int q2 = 0; q2 < 8; q2++) {
                int kw = khalf * 8 + q2;
                int k16 = kw >> 3, kw8 = kw & 7;
                int line = lbase + (kw8 & 3);
                int ls = line ^ (line >> 3);
                int q = ((kw8 >> 2) << 1) + rbit;
                int o = (tile16 * 2 + k16) * FS + ls * 4 + q;
                sAhi[o] = wh[q2];
                sAlo[o] = wl[q2];
            }
        }
        // ---- stage B [128 rows x 16 words] (rows = n, no bounds needed) ----
        {
            int n = t >> 1, khalf = t & 1;
            size_t base = (size_t)(bn + n) * Kw + (kc >> 1) + khalf * 8;
            uint4 vh0 = *(const uint4*)&Bhi[base];
            uint4 vh1 = *(const uint4*)&Bhi[base + 4];
            uint4 vl0 = *(const uint4*)&Blo[base];
            uint4 vl1 = *(const uint4*)&Blo[base + 4];
            uint32_t wh[8] = {vh0.x, vh0.y, vh0.z, vh0.w, vh1.x, vh1.y, vh1.z, vh1.w};
            uint32_t wl[8] = {vl0.x, vl0.y, vl0.z, vl0.w, vl1.x, vl1.y, vl1.z, vl1.w};
            int bandw = n >> 6, nb = n & 63;
            int sn = nb >> 3, pair = sn >> 1, inner = sn & 1;
            int lbase = (nb & 7) * 4;
#pragma unroll
            for (int q2 = 0; q2 < 8; q2++) {
                int kw = khalf * 8 + q2;
                int k16 = kw >> 3, kw8 = kw & 7;
                int line = lbase + (kw8 & 3);
                int ls = line ^ (line >> 3);
                int q = inner * 2 + (kw8 >> 2);
                int o = ((bandw * 2 + k16) * 4 + pair) * FS + ls * 4 + q;
                sBhi[o] = wh[q2];
                sBlo[o] = wl[q2];
            }
        }
        __syncthreads();

        // ---- MMA: 2 k16 steps ----
#pragma unroll
        for (int k16 = 0; k16 < 2; k16++) {
            uint32_t ahi[2][4], alo[2][4];
#pragma unroll
            for (int sm = 0; sm < 2; sm++) {
                int frag = (wmi * 2 + sm) * 2 + k16;
                uint4 vh = *(const uint4*)&sAhi[frag * FS + lsw * 4];
                ahi[sm][0] = vh.x; ahi[sm][1] = vh.y; ahi[sm][2] = vh.z; ahi[sm][3] = vh.w;
                uint4 vl = *(const uint4*)&sAlo[frag * FS + lsw * 4];
                alo[sm][0] = vl.x; alo[sm][1] = vl.y; alo[sm][2] = vl.z; alo[sm][3] = vl.w;
            }
#pragma unroll
            for (int pair = 0; pair < 4; pair++) {
                int frag = ((band * 2 + k16) * 4 + pair) * FS + lsw * 4;
                uint4 vbh = *(const uint4*)&sBhi[frag];
                uint4 vbl = *(const uint4*)&sBlo[frag];
                uint32_t bhe[2] = { vbh.x, vbh.y }, bho[2] = { vbh.z, vbh.w };
                uint32_t ble[2] = { vbl.x, vbl.y }, blo2[2] = { vbl.z, vbl.w };
#pragma unroll
                for (int sm = 0; sm < 2; sm++) {
                    mma16816(acc[sm][2 * pair],     ahi[sm], bhe);
                    mma16816(acc[sm][2 * pair],     ahi[sm], ble);
                    mma16816(acc[sm][2 * pair],     alo[sm], bhe);
                    mma16816(acc[sm][2 * pair + 1], ahi[sm], bho);
                    mma16816(acc[sm][2 * pair + 1], ahi[sm], blo2);
                    mma16816(acc[sm][2 * pair + 1], alo[sm], bho);
                }
            }
        }
        __syncthreads();
    }

    // ---- epilogue ----
#pragma unroll
    for (int sm = 0; sm < 2; sm++) {
        int r0 = bm + wmi * 32 + sm * 16 + g;
#pragma unroll
        for (int sn = 0; sn < 8; sn++) {
            int col = bn + band * 64 + sn * 8 + tg * 2;
            if (r0 < M)
                *(float2*)&C[(size_t)r0 * Ntot + col] = make_float2(acc[sm][sn][0], acc[sm][sn][1]);
            if (r0 + 8 < M)
                *(float2*)&C[(size_t)(r0 + 8) * Ntot + col] = make_float2(acc[sm][sn][2], acc[sm][sn][3]);
        }
    }
}

__global__ void __launch_bounds__(256)
k_hmma_xw0() {
    hmma_gemm_body(g_xhi, g_xlo, g_w0hi, g_w0lo, g_xw, N_NODES, D_HID, D_IN);
}
__global__ void __launch_bounds__(256)
k_hmma_hw1() {
    hmma_gemm_body(g_hhi, g_hlo, g_w1hi, g_w1lo, g_xw, N_NODES, D_HID, D_HID);
}
__global__ void __launch_bounds__(256)
k_hmma_xrel(float* __restrict__ xrel) {
    hmma_gemm_body(g_hhi, g_hlo, g_anchhi, g_anchlo, xrel, N_NODES, N_PROT, D_HID);
}
__global__ void __launch_bounds__(256)
k_hmma_xrel_scratch() {
    hmma_gemm_body(g_hhi, g_hlo, g_anchhi, g_anchlo, g_xrel_scratch, N_NODES, N_PROT, D_HID);
}

// ------- GCN aggregation: precomputed weights, x4 unroll, writes hi/lo planes
__global__ void k_aggregate(const float* __restrict__ bias, int do_relu, int do_norm) {
    int node = blockIdx.x;
    int t = threadIdx.x;  // 64 threads x float4 = 256 cols
    int beg = g_rowptr[node], end = g_rowptr[node + 1];
    const float4* xw4 = (const float4*)g_xw;
    float4 acc = make_float4(0.f, 0.f, 0.f, 0.f);

    int e = beg;
    for (; e + 4 <= end; e += 4) {
        int   s0 = g_csr_src[e],   s1 = g_csr_src[e+1];
        int   s2 = g_csr_src[e+2], s3 = g_csr_src[e+3];
        float w0 = g_csr_w[e],     w1 = g_csr_w[e+1];
        float w2 = g_csr_w[e+2],   w3 = g_csr_w[e+3];
        float4 v0 = xw4[(size_t)s0 * 64 + t];
        float4 v1 = xw4[(size_t)s1 * 64 + t];
        float4 v2 = xw4[(size_t)s2 * 64 + t];
        float4 v3 = xw4[(size_t)s3 * 64 + t];
        acc.x += w0*v0.x + w1*v1.x + w2*v2.x + w3*v3.x;
        acc.y += w0*v0.y + w1*v1.y + w2*v2.y + w3*v3.y;
        acc.z += w0*v0.z + w1*v1.z + w2*v2.z + w3*v3.z;
        acc.w += w0*v0.w + w1*v1.w + w2*v2.w + w3*v3.w;
    }
    for (; e < end; e++) {
        int s = g_csr_src[e];
        float w = g_csr_w[e];
        float4 v = xw4[(size_t)s * 64 + t];
        acc.x += w*v.x; acc.y += w*v.y; acc.z += w*v.z; acc.w += w*v.w;
    }
    {   // self loop
        float dn = g_dis[node];
        float w = dn * dn;
        float4 v = xw4[(size_t)node * 64 + t];
        acc.x += w*v.x; acc.y += w*v.y; acc.z += w*v.z; acc.w += w*v.w;
    }
    float4 bv = ((const float4*)bias)[t];
    acc.x += bv.x; acc.y += bv.y; acc.z += bv.z; acc.w += bv.w;
    if (do_relu) {
        acc.x = fmaxf(acc.x, 0.f); acc.y = fmaxf(acc.y, 0.f);
        acc.z = fmaxf(acc.z, 0.f); acc.w = fmaxf(acc.w, 0.f);
    }
    if (do_norm) {   // fused L2 row-normalize
        float s = acc.x*acc.x + acc.y*acc.y + acc.z*acc.z + acc.w*acc.w;
#pragma unroll
        for (int off = 16; off >= 1; off >>= 1)
            s += __shfl_xor_sync(0xFFFFFFFFu, s, off);
        __shared__ float ws[2];
        if ((t & 31) == 0) ws[t >> 5] = s;
        __syncthreads();
        s = ws[0] + ws[1];
        float r = 1.0f / sqrtf(s);
        acc.x *= r; acc.y *= r; acc.z *= r; acc.w *= r;
    }
    // write bf16 hi/lo planes (2 words per thread per plane)
    uint32_t h0, l0, h1, l1;
    split2(acc.x, acc.y, h0, l0);
    split2(acc.z, acc.w, h1, l1);
    *(uint2*)&g_hhi[(size_t)node * 128 + 2 * t] = make_uint2(h0, h1);
    *(uint2*)&g_hlo[(size_t)node * 128 + 2 * t] = make_uint2(l0, l1);
}

// ---------------- anchor gather (planes) -------------------------------------
__global__ void k_gather_anchors(const int* __restrict__ prot) {
    int p = blockIdx.x;
    int t = threadIdx.x;  // 128 threads = 128 words
    int nl = prot[p];
    int node = (nl >= 0 && nl < N_NODES) ? nl : 0;
    g_anchhi[p * 128 + t] = g_hhi[(size_t)node * 128 + t];
    g_anchlo[p * 128 + t] = g_hlo[(size_t)node * 128 + t];
}

// ---------------- prototype head: log_softmax(lin(anchors)) ------------------
__global__ void k_proto_head(const float* __restrict__ Wl1, const float* __restrict__ bl1,
                             const float* __restrict__ Wl2, const float* __restrict__ bl2,
                             float* __restrict__ out_proto_dst, int write_out) {
    int p = blockIdx.x;
    int t = threadIdx.x;  // 256
    __shared__ float a[D_HID];
    __shared__ float h1[D_HID];
    __shared__ float z[N_CLS];
    {   // reconstruct fp32 anchor value: hi + lo
        uint32_t wh = g_anchhi[p * 128 + (t >> 1)];
        uint32_t wl = g_anchlo[p * 128 + (t >> 1)];
        __nv_bfloat16 bh = ((const __nv_bfloat16*)&wh)[t & 1];
        __nv_bfloat16 bl = ((const __nv_bfloat16*)&wl)[t & 1];
        a[t] = __bfloat162float(bh) + __bfloat162float(bl);
    }
    __syncthreads();
    float s = bl1[t];
#pragma unroll 4
    for (int k = 0; k < D_HID; k++) s += a[k] * Wl1[(size_t)k * D_HID + t];
    h1[t] = fmaxf(s, 0.0f);
    __syncthreads();
    if (t < N_CLS) {
        float s2 = bl2[t];
#pragma unroll 4
        for (int k = 0; k < D_HID; k++) s2 += h1[k] * Wl2[(size_t)k * N_CLS + t];
        z[t] = s2;
    }
    __syncthreads();
    if (t < N_CLS) {
        float m = z[0];
#pragma unroll
        for (int j = 1; j < N_CLS; j++) m = fmaxf(m, z[j]);
        float se = 0.f;
#pragma unroll
        for (int j = 0; j < N_CLS; j++) se += expf(z[j] - m);
        float v = z[t] - m - logf(se);
        g_outproto[(size_t)p * N_CLS + t] = v;
        if (write_out) out_proto_dst[(size_t)p * N_CLS + t] = v;
    }
}

// ---------------- out = log_softmax(x_rel @ out_proto) -----------------------
__device__ __forceinline__ void out_head_body(const float* __restrict__ xr_base,
                                              float* __restrict__ out) {
    __shared__ float ps[N_PROT * N_CLS];  // 32KB
    __shared__ float z[8][N_CLS];
    int t = threadIdx.x;
    for (int i = t; i < N_PROT * N_CLS; i += 128) ps[i] = g_outproto[i];
    __syncthreads();
    int g = t >> 4;
    int c = t & 15;
    int node = blockIdx.x * 8 + g;
    const float* xr = xr_base + (size_t)node * N_PROT;
    float s0 = 0.f, s1 = 0.f, s2 = 0.f, s3 = 0.f;
    for (int p = 0; p < N_PROT; p += 4) {
        s0 += xr[p + 0] * ps[(p + 0) * N_CLS + c];
        s1 += xr[p + 1] * ps[(p + 1) * N_CLS + c];
        s2 += xr[p + 2] * ps[(p + 2) * N_CLS + c];
        s3 += xr[p + 3] * ps[(p + 3) * N_CLS + c];
    }
    float s = (s0 + s1) + (s2 + s3);
    z[g][c] = s;
    __syncthreads();
    float m = z[g][0];
#pragma unroll
    for (int j = 1; j < N_CLS; j++) m = fmaxf(m, z[g][j]);
    float se = 0.f;
#pragma unroll
    for (int j = 0; j < N_CLS; j++) se += expf(z[g][j] - m);
    out[(size_t)node * N_CLS + c] = s - m - logf(se);
}

__global__ void k_out_head(const float* __restrict__ xrel, float* __restrict__ out) {
    out_head_body(xrel, out);
}
__global__ void k_out_head_scratch(float* __restrict__ out) {
    out_head_body(g_xrel_scratch, out);
}

// ---------------- launcher ----------------
extern "C" void kernel_launch(void* const* d_in, const int* in_sizes, int n_in,
                              void* d_out, int out_size) {
    const float* x    = (const float*)d_in[0];
    const int*   ei   = (const int*)d_in[1];     // int32
    const int*   prot = (const int*)d_in[2];     // int32

    int wbase = (in_sizes[3] <= 1) ? 4 : 3;
    const float* W0  = (const float*)d_in[wbase + 0];
    const float* b0  = (const float*)d_in[wbase + 1];
    const float* W1  = (const float*)d_in[wbase + 2];
    const float* b1  = (const float*)d_in[wbase + 3];
    const float* Wl1 = (const float*)d_in[wbase + 4];
    const float* bl1 = (const float*)d_in[wbase + 5];
    const float* Wl2 = (const float*)d_in[wbase + 6];
    const float* bl2 = (const float*)d_in[wbase + 7];

    const size_t SZ_OUT   = (size_t)N_NODES * N_CLS;
    const size_t SZ_XREL  = (size_t)N_NODES * N_PROT;
    const size_t SZ_PROTO = (size_t)N_PROT * N_CLS;

    float* out = (float*)d_out;
    bool full = ((size_t)out_size >= SZ_OUT + SZ_XREL + SZ_PROTO);
    float* xrel = nullptr;
    float* out_proto = nullptr;
    if (full) {
        xrel      = out + SZ_OUT;
        out_proto = xrel + SZ_XREL;
    }

    const int* src = ei;
    const int* dst = ei + N_EDGES;

    const int MTILES = (N_NODES + 127) / 128;   // 391
    dim3 g1(D_HID / 128, MTILES);               // (2, 391)
    dim3 g2(N_PROT / 128, MTILES);              // (4, 391)

    // order chosen so k_hmma_xw0 stays at launch index 3 (ncu capture slot)
    k_split_x<<<(N_NODES * (D_IN / 2) + 255) / 256, 256>>>(x);          // 0
    k_split_w<<<(256 * (D_IN / 2) + 256 * (D_HID / 2) + 255) / 256, 256>>>(W0, W1); // 1
    k_zero_counts<<<(N_NODES + 255) / 256, 256>>>();                    // 2
    k_hmma_xw0<<<g1, 256>>>();                                          // 3 <- profiled
    k_count_deg<<<(N_EDGES + 255) / 256, 256>>>(dst);
    k_dis<<<(N_NODES + 255) / 256, 256>>>();
    k_scan_partial<<<N_TILES, SCAN_TILE>>>();
    k_scan_offsets<<<1, 32>>>();
    k_scan_final<<<N_TILES, SCAN_TILE>>>();
    k_fill_csr<<<(N_EDGES + 255) / 256, 256>>>(src, dst);

    // layer 0: h = relu(aggregate(xw) + b0)  -> hi/lo planes
    k_aggregate<<<N_NODES, 64>>>(b0, 1, 0);
    // layer 1: h = normalize(aggregate(h @ W1) + b1) -> hi/lo planes
    k_hmma_hw1<<<g1, 256>>>();
    k_aggregate<<<N_NODES, 64>>>(b1, 0, 1);

    k_gather_anchors<<<N_PROT, 128>>>(prot);
    k_proto_head<<<N_PROT, 256>>>(Wl1, bl1, Wl2, bl2, out_proto, full ? 1 : 0);

    if (full) {
        k_hmma_xrel<<<g2, 256>>>(xrel);
        k_out_head<<<N_NODES / 8, 128>>>(xrel, out);
    } else {
        k_hmma_xrel_scratch<<<g2, 256>>>();
        k_out_head_scratch<<<N_NODES / 8, 128>>>(out);
    }
}